// round 13
// baseline (speedup 1.0000x reference)
#include <cuda_runtime.h>
#include <cuda_fp16.h>
#include <cstdint>
#include <cstddef>

#define VOCAB 32000
#define EMB   256
#define HID   512
#define FEAT  1024
#define BATCH 32
#define TT    100
#define M_ROWS (TT*BATCH)      // 3200
#define NBLK_LSTM 128

// N-partition: mma covers [0, 25600), SIMT covers [25600, 32000)
#define N_SPLIT 25600
#define MMA_TPY 200                 // 25600/128 n-tiles per y
#define MMA_TILES (MMA_TPY*25)      // 5000
#define SIMT_TPY 100                // 6400/64 n-subtiles per y
#define SIMT_TILES (SIMT_TPY*25)    // 2500
typedef unsigned long long ull;

// ---------------------------------------------------------------------------
// device scratch
// ---------------------------------------------------------------------------
__device__ float g_pooled[BATCH*FEAT];
__device__ float g_xg[(size_t)M_ROWS * 4 * HID];
__device__ float g_hall[(size_t)M_ROWS * HID];     // fp32 h (SIMT A)
__device__ float g_hping[2][BATCH*HID];
__device__ int   g_tok[M_ROWS];
__device__ unsigned g_barrier;
__device__ int   g_tile;      // mma queue
__device__ int   g_tile2;     // SIMT queue

__device__ __half g_wv_f16[(size_t)VOCAB * HID];   // fp16 weights (mma B)
__device__ __half g_h_f16[(size_t)M_ROWS * HID];   // fp16 h (mma A)

// ---------------------------------------------------------------------------
// helpers
// ---------------------------------------------------------------------------
__device__ __forceinline__ uint32_t smem_u32(const void* p) {
    uint32_t a;
    asm("{ .reg .u64 t; cvta.to.shared.u64 t, %1; cvt.u32.u64 %0, t; }" : "=r"(a) : "l"(p));
    return a;
}
__device__ __forceinline__ void cp_async16(uint32_t dst, const void* src) {
    asm volatile("cp.async.cg.shared.global [%0], [%1], 16;" :: "r"(dst), "l"(src) : "memory");
}
#define CP_ASYNC_COMMIT() asm volatile("cp.async.commit_group;" ::: "memory")
#define CP_ASYNC_WAIT(n)  asm volatile("cp.async.wait_group %0;" :: "n"(n) : "memory")

#define BAR_VOCAB() asm volatile("bar.sync 1, 512;" ::: "memory")
#define BAR_LSTM()  asm volatile("bar.sync 2, 128;" ::: "memory")
#define BAR_SIMT()  asm volatile("bar.sync 3, 256;" ::: "memory")

__device__ __forceinline__ void ldsm_x4(uint32_t& r0, uint32_t& r1, uint32_t& r2, uint32_t& r3,
                                        uint32_t addr) {
    asm volatile("ldmatrix.sync.aligned.m8n8.x4.shared.b16 {%0,%1,%2,%3}, [%4];"
                 : "=r"(r0), "=r"(r1), "=r"(r2), "=r"(r3) : "r"(addr));
}
__device__ __forceinline__ void mma_f16(float* c, uint32_t a0, uint32_t a1, uint32_t a2, uint32_t a3,
                                        uint32_t b0, uint32_t b1) {
    asm volatile("mma.sync.aligned.m16n8k16.row.col.f32.f16.f16.f32 "
                 "{%0,%1,%2,%3}, {%4,%5,%6,%7}, {%8,%9}, {%0,%1,%2,%3};"
                 : "+f"(c[0]), "+f"(c[1]), "+f"(c[2]), "+f"(c[3])
                 : "r"(a0), "r"(a1), "r"(a2), "r"(a3), "r"(b0), "r"(b1));
}

__device__ __forceinline__ ull pack2(float x, float y) {
    ull r;
    asm("mov.b64 %0, {%1, %2};" : "=l"(r) : "r"(__float_as_uint(x)), "r"(__float_as_uint(y)));
    return r;
}
__device__ __forceinline__ void ffma2(ull& d, ull a, ull b) {
    asm("fma.rn.f32x2 %0, %1, %2, %3;" : "=l"(d) : "l"(a), "l"(b), "l"(d));
}
__device__ __forceinline__ float sum2(ull p) {
    return __uint_as_float((unsigned)p) + __uint_as_float((unsigned)(p >> 32));
}

// ---------------------------------------------------------------------------
// K0: prep + pool
// ---------------------------------------------------------------------------
__global__ void prep_pool_kernel(const int* __restrict__ reports, const float* __restrict__ feat) {
    int i = blockIdx.x * blockDim.x + threadIdx.x;
    if (i == 0) { g_barrier = 0u; g_tile = 0; g_tile2 = 0; }
    if (i < M_ROWS) {
        int t = i >> 5, b = i & 31;
        g_tok[i] = (t == 0) ? 1 : reports[b * TT + (t - 1)];
    }
    if (i < BATCH * FEAT) {
        const float* p = feat + (size_t)i * 49;
        float s = 0.f;
        #pragma unroll
        for (int j = 0; j < 49; j++) s += p[j];
        g_pooled[i] = s * (1.f / 49.f);
    }
}

// ---------------------------------------------------------------------------
// K1: h0 + Wv fp16 convert
// ---------------------------------------------------------------------------
#define H0_BLOCKS 64
__global__ void h0_cvt_kernel(const float* __restrict__ fc_w, const float* __restrict__ fc_b,
                              const float* __restrict__ wv, __half* __restrict__ wv16) {
    if (blockIdx.x < H0_BLOCKS) {
        int i = blockIdx.x * blockDim.x + threadIdx.x;
        if (i >= BATCH * HID) return;
        int b = i >> 9, j = i & 511;
        const float* pw = fc_w + (size_t)j * FEAT;
        const float* pp = g_pooled + (size_t)b * FEAT;
        float acc = fc_b[j];
        #pragma unroll 4
        for (int k = 0; k < FEAT; k++) acc = fmaf(pw[k], pp[k], acc);
        g_hping[0][b * HID + j] = acc;
    } else {
        int i = (blockIdx.x - H0_BLOCKS) * blockDim.x + threadIdx.x;
        if (i >= N_SPLIT * HID / 4) return;     // only mma's share needs fp16
        float4 v = reinterpret_cast<const float4*>(wv)[i];
        reinterpret_cast<__half2*>(wv16)[i*2]   = __halves2half2(__float2half_rn(v.x), __float2half_rn(v.y));
        reinterpret_cast<__half2*>(wv16)[i*2+1] = __halves2half2(__float2half_rn(v.z), __float2half_rn(v.w));
    }
}

// ---------------------------------------------------------------------------
// K2: SIMT fp32 GEMM (gates)
// ---------------------------------------------------------------------------
__global__ __launch_bounds__(256)
void gemm_gates_kernel(const float* __restrict__ Asrc, const float* __restrict__ Bsrc,
                       const float* __restrict__ bias0, const float* __restrict__ bias1,
                       float* __restrict__ C, int N, int K, const int* __restrict__ gidx)
{
    __shared__ float As[16 * 132];
    __shared__ float Bs[16 * 132];
    const int tid = threadIdx.x;
    const int n0 = blockIdx.x * 128;
    const int m0 = blockIdx.y * 128;
    const int ty = tid >> 4;
    const int tx = tid & 15;

    ull acc[8][4];
    #pragma unroll
    for (int i = 0; i < 8; i++)
        #pragma unroll
        for (int j = 0; j < 4; j++) acc[i][j] = 0ull;

    const int ml = tid >> 2;
    const int kq = (tid & 3) * 4;
    const float* arow0 = Asrc + (size_t)gidx[m0 + ml] * K;
    const float* arow1 = Asrc + (size_t)gidx[m0 + ml + 64] * K;
    const float* brow0 = Bsrc + (size_t)(n0 + ml) * K;
    const float* brow1 = Bsrc + (size_t)(n0 + ml + 64) * K;

    for (int k0 = 0; k0 < K; k0 += 16) {
        float4 a0  = *reinterpret_cast<const float4*>(arow0 + k0 + kq);
        float4 a1  = *reinterpret_cast<const float4*>(arow1 + k0 + kq);
        float4 bb0 = *reinterpret_cast<const float4*>(brow0 + k0 + kq);
        float4 bb1 = *reinterpret_cast<const float4*>(brow1 + k0 + kq);
        __syncthreads();
        As[(kq+0)*132 + ml] = a0.x;  As[(kq+1)*132 + ml] = a0.y;
        As[(kq+2)*132 + ml] = a0.z;  As[(kq+3)*132 + ml] = a0.w;
        As[(kq+0)*132 + ml+64] = a1.x;  As[(kq+1)*132 + ml+64] = a1.y;
        As[(kq+2)*132 + ml+64] = a1.z;  As[(kq+3)*132 + ml+64] = a1.w;
        Bs[(kq+0)*132 + ml] = bb0.x; Bs[(kq+1)*132 + ml] = bb0.y;
        Bs[(kq+2)*132 + ml] = bb0.z; Bs[(kq+3)*132 + ml] = bb0.w;
        Bs[(kq+0)*132 + ml+64] = bb1.x; Bs[(kq+1)*132 + ml+64] = bb1.y;
        Bs[(kq+2)*132 + ml+64] = bb1.z; Bs[(kq+3)*132 + ml+64] = bb1.w;
        __syncthreads();

        #pragma unroll
        for (int kk = 0; kk < 16; kk++) {
            const float* ar = As + kk*132 + ty*8;
            const float* br = Bs + kk*132 + tx*8;
            float4 av0 = *reinterpret_cast<const float4*>(ar);
            float4 av1 = *reinterpret_cast<const float4*>(ar + 4);
            float4 bv0 = *reinterpret_cast<const float4*>(br);
            float4 bv1 = *reinterpret_cast<const float4*>(br + 4);
            ull bp0 = pack2(bv0.x, bv0.y);
            ull bp1 = pack2(bv0.z, bv0.w);
            ull bp2 = pack2(bv1.x, bv1.y);
            ull bp3 = pack2(bv1.z, bv1.w);
            float aa[8] = {av0.x, av0.y, av0.z, av0.w, av1.x, av1.y, av1.z, av1.w};
            #pragma unroll
            for (int i = 0; i < 8; i++) {
                ull ap = pack2(aa[i], aa[i]);
                ffma2(acc[i][0], ap, bp0);
                ffma2(acc[i][1], ap, bp1);
                ffma2(acc[i][2], ap, bp2);
                ffma2(acc[i][3], ap, bp3);
            }
        }
    }

    float bias[8];
    #pragma unroll
    for (int j = 0; j < 8; j++) {
        int n = n0 + tx*8 + j;
        bias[j] = bias0[n] + bias1[n];
    }
    #pragma unroll
    for (int i = 0; i < 8; i++) {
        int m = m0 + ty*8 + i;
        size_t base = (size_t)m * (size_t)N + (size_t)(n0 + tx*8);
        float o[8];
        #pragma unroll
        for (int j = 0; j < 4; j++) {
            o[2*j]   = __uint_as_float((unsigned)(acc[i][j]))       + bias[2*j];
            o[2*j+1] = __uint_as_float((unsigned)(acc[i][j] >> 32)) + bias[2*j+1];
        }
        *reinterpret_cast<float4*>(C + base)     = make_float4(o[0], o[1], o[2], o[3]);
        *reinterpret_cast<float4*>(C + base + 4) = make_float4(o[4], o[5], o[6], o[7]);
    }
}

// ---------------------------------------------------------------------------
// K3: fused persistent kernel. 148 blocks x 896 threads.
//   warps  0-15 (tid   0-511): mma vocab GEMM, n in [0, 25600), tiles 128x128
//   warps 16-23 (tid 512-767): SIMT f32x2 vocab GEMM, n in [25600, 32000), tiles 128x64
//   warps 24-27 (tid 768-895): LSTM (blocks 0..127), highest wid -> priority
// ---------------------------------------------------------------------------
#define WS_STRIDE 516
#define LSTM_SMEM_BYTES 101248
#define VG_STAGE 32768
#define SIMT_SMEM_OFF (LSTM_SMEM_BYTES + 2*VG_STAGE)
#define SIMT_AS_FLOATS (16*132)
#define SIMT_BS_FLOATS (16*68)
#define FUSED_SMEM (SIMT_SMEM_OFF + (SIMT_AS_FLOATS + SIMT_BS_FLOATS)*4)

__device__ __forceinline__ void lstm_role(float* sm, const float* __restrict__ Whh, int ltid) {
    float* ws  = sm;
    float* hs  = sm + 16*WS_STRIDE;
    float* gsm = sm + 16*WS_STRIDE + 32*WS_STRIDE;

    const int n0 = blockIdx.x * 4;

    for (int lr = 0; lr < 16; lr++) {
        int u = lr >> 2, g = lr & 3;
        const float* src = Whh + (size_t)(g * HID + n0 + u) * HID;
        for (int k = ltid; k < HID; k += 128) ws[lr * WS_STRIDE + k] = src[k];
    }

    const int rp = (ltid & 1) + ((ltid >> 5) << 1);
    const int r0 = rp * 2, r1 = r0 + 1;
    const int bp = (ltid >> 1) & 15;
    const int b0 = bp * 2, b1 = b0 + 1;
    const int cu = ltid >> 5;
    const int cb = ltid & 31;
    const int g0 = (r0 & 3) * HID + n0 + (r0 >> 2);
    const int g1 = (r1 & 3) * HID + n0 + (r1 >> 2);
    float c_reg = 0.f;

    BAR_LSTM();

    for (int t = 0; t < TT; t++) {
        const size_t xt = (size_t)t * BATCH * (4*HID);
        float x00 = __ldcg(&g_xg[xt + (size_t)b0 * (4*HID) + g0]);
        float x01 = __ldcg(&g_xg[xt + (size_t)b1 * (4*HID) + g0]);
        float x10 = __ldcg(&g_xg[xt + (size_t)b0 * (4*HID) + g1]);
        float x11 = __ldcg(&g_xg[xt + (size_t)b1 * (4*HID) + g1]);

        const float* hin = g_hping[t & 1];
        #pragma unroll 4
        for (int j = 0; j < 32; j++) {
            float4 v = __ldcg(reinterpret_cast<const float4*>(hin + j * HID + ltid * 4));
            *reinterpret_cast<float4*>(hs + j * WS_STRIDE + ltid * 4) = v;
        }
        BAR_LSTM();

        const ulonglong2* w0 = reinterpret_cast<const ulonglong2*>(ws + r0 * WS_STRIDE);
        const ulonglong2* w1 = reinterpret_cast<const ulonglong2*>(ws + r1 * WS_STRIDE);
        const ulonglong2* ha = reinterpret_cast<const ulonglong2*>(hs + b0 * WS_STRIDE);
        const ulonglong2* hb = reinterpret_cast<const ulonglong2*>(hs + b1 * WS_STRIDE);
        ull p00 = 0ull, p01 = 0ull, p10 = 0ull, p11 = 0ull;
        #pragma unroll 8
        for (int k = 0; k < HID/4; k++) {
            ulonglong2 wa = w0[k], wb = w1[k];
            ulonglong2 va = ha[k], vb = hb[k];
            ffma2(p00, wa.x, va.x); ffma2(p00, wa.y, va.y);
            ffma2(p01, wa.x, vb.x); ffma2(p01, wa.y, vb.y);
            ffma2(p10, wb.x, va.x); ffma2(p10, wb.y, va.y);
            ffma2(p11, wb.x, vb.x); ffma2(p11, wb.y, vb.y);
        }
        gsm[r0*33 + b0] = sum2(p00) + x00;
        gsm[r0*33 + b1] = sum2(p01) + x01;
        gsm[r1*33 + b0] = sum2(p10) + x10;
        gsm[r1*33 + b1] = sum2(p11) + x11;
        BAR_LSTM();

        {
            float iv = gsm[(cu*4 + 0)*33 + cb];
            float fv = gsm[(cu*4 + 1)*33 + cb];
            float gv = gsm[(cu*4 + 2)*33 + cb];
            float ov = gsm[(cu*4 + 3)*33 + cb];
            iv = 1.f / (1.f + __expf(-iv));
            fv = 1.f / (1.f + __expf(-fv));
            ov = 1.f / (1.f + __expf(-ov));
            gv = tanhf(gv);
            c_reg = fv * c_reg + iv * gv;
            float hn = ov * tanhf(c_reg);
            int nidx = n0 + cu;
            size_t hrow = ((size_t)t * BATCH + cb) * HID + nidx;
            __stcg(&g_hping[(t + 1) & 1][cb * HID + nidx], hn);
            __stcg(&g_hall[hrow], hn);
            __stcg(reinterpret_cast<__half*>(&g_h_f16[hrow]), __float2half_rn(hn));
        }

        __threadfence();
        BAR_LSTM();
        if (ltid == 0) atomicAdd(&g_barrier, 1u);
        if (t + 1 < TT) {
            if (ltid == 0) {
                unsigned target = (unsigned)((t + 1) * NBLK_LSTM);
                while (*((volatile unsigned*)&g_barrier) < target) { __nanosleep(32); }
            }
            BAR_LSTM();
            __threadfence();
        }
    }
}

// ---- mma vocab role: 16 warps, tiles 128x128, warp tile 32x32, f32 acc ----
__device__ __forceinline__ void vocab_mma_role(char* vsm_raw, const float* __restrict__ bv,
                                               float* __restrict__ out, int tid) {
    __shared__ int s_ti;
    const uint32_t smem = smem_u32(vsm_raw);
    const int wid  = tid >> 5;
    const int lane = tid & 31;
    const int wm   = wid >> 2;          // 0..3
    const int wn   = wid & 3;           // 0..3

    for (;;) {
        if (tid == 0) s_ti = atomicAdd(&g_tile, 1);
        BAR_VOCAB();
        const int ti = s_ti;
        if (ti >= MMA_TILES) break;
        const int yy = ti / MMA_TPY;
        const int n0 = (ti - yy * MMA_TPY) * 128;
        const int m0 = yy * 128;

        if (tid == 0) {
            unsigned need = (unsigned)((yy * 4 + 4) * NBLK_LSTM);
            while (*((volatile unsigned*)&g_barrier) < need) { __nanosleep(128); }
        }
        BAR_VOCAB();
        __threadfence();

        float acc[2][4][4];
        #pragma unroll
        for (int i = 0; i < 2; i++)
            #pragma unroll
            for (int j = 0; j < 4; j++)
                #pragma unroll
                for (int q = 0; q < 4; q++) acc[i][j][q] = 0.f;

        auto load_chunk = [&](int chunk) {
            const uint32_t stage = smem + (uint32_t)(chunk & 1) * VG_STAGE;
            const int kbase = chunk * 64;
            #pragma unroll
            for (int j = 0; j < 4; j++) {
                int i = tid + j * 512;          // 0..2047
                const __half* gb;
                int grow;
                uint32_t doff;
                int cc;
                if (i < 1024) {                  // A: 128 rows x 8 chunks of 16B
                    int r  = (i >> 3) & 127;
                    cc = i & 7;
                    gb = g_h_f16;
                    grow = m0 + r;
                    doff = (uint32_t)(r * 128) + (uint32_t)(((cc ^ (r & 7)) * 16));
                } else {                         // B: 128 rows x 8 chunks
                    int jj = i - 1024;
                    int r  = (jj >> 3) & 127;
                    cc = jj & 7;
                    gb = g_wv_f16;
                    grow = n0 + r;
                    doff = 16384u + (uint32_t)(r * 128) + (uint32_t)(((cc ^ (r & 7)) * 16));
                }
                cp_async16(stage + doff, gb + (size_t)grow * HID + kbase + cc * 8);
            }
            CP_ASYNC_COMMIT();
        };

        load_chunk(0);

        for (int chunk = 0; chunk < 8; chunk++) {
            if (chunk + 1 < 8) { load_chunk(chunk + 1); CP_ASYNC_WAIT(1); }
            else               { CP_ASYNC_WAIT(0); }
            BAR_VOCAB();

            const uint32_t stage = smem + (uint32_t)(chunk & 1) * VG_STAGE;
            const uint32_t aBase = stage;
            const uint32_t bBase = stage + 16384u;

            #pragma unroll
            for (int ks = 0; ks < 4; ks++) {
                uint32_t ah[2][4];
                #pragma unroll
                for (int mt = 0; mt < 2; mt++) {
                    int row = wm * 32 + mt * 16 + (lane & 7) + ((lane >> 3) & 1) * 8;
                    int ch  = ks * 2 + (lane >> 4);
                    uint32_t off = (uint32_t)(row * 128) + (uint32_t)((ch ^ (row & 7)) * 16);
                    ldsm_x4(ah[mt][0], ah[mt][1], ah[mt][2], ah[mt][3], aBase + off);
                }
                #pragma unroll
                for (int p = 0; p < 2; p++) {
                    int g   = lane >> 3;
                    int row = wn * 32 + p * 16 + (g & 1) * 8 + (lane & 7);
                    int ch  = ks * 2 + (g >> 1);
                    uint32_t off = (uint32_t)(row * 128) + (uint32_t)((ch ^ (row & 7)) * 16);
                    uint32_t r0, r1, r2, r3;
                    ldsm_x4(r0, r1, r2, r3, bBase + off);
                    uint32_t bh[2][2];
                    bh[0][0] = r0; bh[0][1] = r2;
                    bh[1][0] = r1; bh[1][1] = r3;
                    #pragma unroll
                    for (int mt = 0; mt < 2; mt++) {
                        #pragma unroll
                        for (int q = 0; q < 2; q++) {
                            int nt = p * 2 + q;
                            mma_f16(acc[mt][nt], ah[mt][0], ah[mt][1], ah[mt][2], ah[mt][3],
                                    bh[q][0], bh[q][1]);
                        }
                    }
                }
            }
            BAR_VOCAB();
        }

        #pragma unroll
        for (int mt = 0; mt < 2; mt++) {
            int gm0 = m0 + wm * 32 + mt * 16 + (lane >> 2);
            int gm1 = gm0 + 8;
            size_t ob0 = ((size_t)(gm0 & 31) * TT + (size_t)(gm0 >> 5)) * (size_t)VOCAB;
            size_t ob1 = ((size_t)(gm1 & 31) * TT + (size_t)(gm1 >> 5)) * (size_t)VOCAB;
            #pragma unroll
            for (int nt = 0; nt < 4; nt++) {
                int gn = n0 + wn * 32 + nt * 8 + (lane & 3) * 2;
                float bv0 = __ldg(bv + gn), bv1 = __ldg(bv + gn + 1);
                float2 v0 = make_float2(acc[mt][nt][0] + bv0, acc[mt][nt][1] + bv1);
                float2 v1 = make_float2(acc[mt][nt][2] + bv0, acc[mt][nt][3] + bv1);
                *reinterpret_cast<float2*>(out + ob0 + gn) = v0;
                *reinterpret_cast<float2*>(out + ob1 + gn) = v1;
            }
        }
    }
}

// ---- SIMT f32x2 vocab role: 8 warps, tiles 128m x 64n, fp32 exact ----
__device__ __forceinline__ void vocab_simt_role(float* As, const float* __restrict__ Wv,
                                                const float* __restrict__ bv,
                                                float* __restrict__ out, int st) {
    __shared__ int s_ti2;
    float* Bs = As + SIMT_AS_FLOATS;
    const int ty = st >> 4;             // 0..15 -> 8 rows each
    const int tx = st & 15;             // 0..15 -> 4 cols each

    for (;;) {
        if (st == 0) s_ti2 = atomicAdd(&g_tile2, 1);
        BAR_SIMT();
        const int ti = s_ti2;
        if (ti >= SIMT_TILES) break;
        const int yy = ti / SIMT_TPY;
        const int n0 = N_SPLIT + (ti - yy * SIMT_TPY) * 64;
        const int m0 = yy * 128;

        if (st == 0) {
            unsigned need = (unsigned)((yy * 4 + 4) * NBLK_LSTM);
            while (*((volatile unsigned*)&g_barrier) < need) { __nanosleep(128); }
        }
        BAR_SIMT();
        __threadfence();

        ull acc[8][2];
        #pragma unroll
        for (int i = 0; i < 8; i++) { acc[i][0] = 0ull; acc[i][1] = 0ull; }

        const int mla = st >> 1;            // A row 0..127
        const int kqa = (st & 1) * 8;       // A k offset 0 or 8
        const int mlb = st >> 2;            // B row 0..63
        const int kqb = (st & 3) * 4;       // B k offset
        const float* arow = g_hall + (size_t)(m0 + mla) * HID;
        const float* brow = Wv + (size_t)(n0 + mlb) * HID;

        for (int k0 = 0; k0 < HID; k0 += 16) {
            float4 a0 = __ldcg(reinterpret_cast<const float4*>(arow + k0 + kqa));
            float4 a1 = __ldcg(reinterpret_cast<const float4*>(arow + k0 + kqa + 4));
            float4 b0 = __ldg(reinterpret_cast<const float4*>(brow + k0 + kqb));
            BAR_SIMT();
            As[(kqa+0)*132 + mla] = a0.x; As[(kqa+1)*132 + mla] = a0.y;
            As[(kqa+2)*132 + mla] = a0.z; As[(kqa+3)*132 + mla] = a0.w;
            As[(kqa+4)*132 + mla] = a1.x; As[(kqa+5)*132 + mla] = a1.y;
            As[(kqa+6)*132 + mla] = a1.z; As[(kqa+7)*132 + mla] = a1.w;
            Bs[(kqb+0)*68 + mlb] = b0.x; Bs[(kqb+1)*68 + mlb] = b0.y;
            Bs[(kqb+2)*68 + mlb] = b0.z; Bs[(kqb+3)*68 + mlb] = b0.w;
            BAR_SIMT();

            #pragma unroll
            for (int kk = 0; kk < 16; kk++) {
                const float* ar = As + kk*132 + ty*8;
                const float* br = Bs + kk*68 + tx*4;
                float4 av0 = *reinterpret_cast<const float4*>(ar);
                float4 av1 = *reinterpret_cast<const float4*>(ar + 4);
                float4 bb  = *reinterpret_cast<const float4*>(br);
                ull bp0 = pack2(bb.x, bb.y);
                ull bp1 = pack2(bb.z, bb.w);
                float aa[8] = {av0.x, av0.y, av0.z, av0.w, av1.x, av1.y, av1.z, av1.w};
                #pragma unroll
                for (int i = 0; i < 8; i++) {
                    ull ap = pack2(aa[i], aa[i]);
                    ffma2(acc[i][0], ap, bp0);
                    ffma2(acc[i][1], ap, bp1);
                }
            }
        }

        // epilogue: 8 rows x 4 cols, permuted, +bias
        float bias[4];
        #pragma unroll
        for (int j = 0; j < 4; j++) bias[j] = __ldg(bv + n0 + tx*4 + j);
        #pragma unroll
        for (int i = 0; i < 8; i++) {
            int m = m0 + ty*8 + i;
            size_t base = ((size_t)(m & 31) * TT + (size_t)(m >> 5)) * (size_t)VOCAB
                        + (size_t)(n0 + tx*4);
            float4 o;
            o.x = __uint_as_float((unsigned)(acc[i][0]))        + bias[0];
            o.y = __uint_as_float((unsigned)(acc[i][0] >> 32))  + bias[1];
            o.z = __uint_as_float((unsigned)(acc[i][1]))        + bias[2];
            o.w = __uint_as_float((unsigned)(acc[i][1] >> 32))  + bias[3];
            *reinterpret_cast<float4*>(out + base) = o;
        }
    }
}

__global__ __launch_bounds__(896, 1)
void fused_kernel(const float* __restrict__ Whh, const float* __restrict__ Wv,
                  const float* __restrict__ bv, float* __restrict__ out)
{
    extern __shared__ char sm_raw[];
    const int tid = threadIdx.x;
    if (tid < 512) {
        vocab_mma_role(sm_raw + LSTM_SMEM_BYTES, bv, out, tid);
    } else if (tid < 768) {
        vocab_simt_role(reinterpret_cast<float*>(sm_raw + SIMT_SMEM_OFF), Wv, bv, out, tid - 512);
    } else {
        if (blockIdx.x < NBLK_LSTM)
            lstm_role(reinterpret_cast<float*>(sm_raw), Whh, tid - 768);
    }
}

// ---------------------------------------------------------------------------
// launch
// ---------------------------------------------------------------------------
extern "C" void kernel_launch(void* const* d_in, const int* in_sizes, int n_in,
                              void* d_out, int out_size) {
    const float* features  = (const float*)d_in[0];
    const int*   reports   = (const int*)  d_in[1];
    const float* emb_table = (const float*)d_in[2];
    const float* fc_w      = (const float*)d_in[3];
    const float* fc_b      = (const float*)d_in[4];
    const float* W_ih      = (const float*)d_in[5];
    const float* b_ih      = (const float*)d_in[6];
    const float* W_hh      = (const float*)d_in[7];
    const float* b_hh      = (const float*)d_in[8];
    const float* Wv        = (const float*)d_in[9];
    const float* bv        = (const float*)d_in[10];
    float* out = (float*)d_out;

    void *p_xg = nullptr, *p_tok = nullptr, *p_wv16 = nullptr;
    cudaGetSymbolAddress(&p_xg,   g_xg);
    cudaGetSymbolAddress(&p_tok,  g_tok);
    cudaGetSymbolAddress(&p_wv16, g_wv_f16);

    cudaFuncSetAttribute(fused_kernel, cudaFuncAttributeMaxDynamicSharedMemorySize, FUSED_SMEM);

    // K0: prep + pool
    prep_pool_kernel<<<(BATCH * FEAT + 255) / 256, 256>>>(reports, features);
    // K1: h0 + Wv->fp16 convert (mma share only)
    {
        int cvt_blocks = (N_SPLIT * HID / 4 + 255) / 256;   // 12800
        h0_cvt_kernel<<<H0_BLOCKS + cvt_blocks, 256>>>(fc_w, fc_b, Wv, (__half*)p_wv16);
    }
    // K2: gates GEMM
    gemm_gates_kernel<<<dim3(4*HID/128, M_ROWS/128), 256>>>(
        emb_table, W_ih, b_ih, b_hh, (float*)p_xg, 4*HID, EMB, (const int*)p_tok);
    // K3: fused persistent LSTM + hybrid (tensor + fma pipe) vocab GEMM
    fused_kernel<<<148, 896, FUSED_SMEM>>>(W_hh, Wv, bv, out);
}

// round 14
// speedup vs baseline: 1.3042x; 1.3042x over previous
#include <cuda_runtime.h>
#include <cuda_fp16.h>
#include <cstdint>
#include <cstddef>

#define VOCAB 32000
#define EMB   256
#define HID   512
#define FEAT  1024
#define BATCH 32
#define TT    100
#define M_ROWS (TT*BATCH)      // 3200
#define NBLK_LSTM 128
#define N_TILES (125*25)       // 3125 vocab tiles (128m x 256n)
#define G_TILES (16*25)        // 400 gates tiles (128m x 128n, K=256)
typedef unsigned long long ull;

// ---------------------------------------------------------------------------
// device scratch
// ---------------------------------------------------------------------------
__device__ float g_pooled[BATCH*FEAT];
__device__ float g_xg[(size_t)M_ROWS * 4 * HID];
__device__ float g_hping[2][BATCH*HID];
__device__ int   g_tok[M_ROWS];
__device__ unsigned g_barrier;
__device__ int   g_tile;          // vocab tile queue
__device__ int   g_gtile;         // gates tile queue
__device__ int   g_xg_ready[25];  // per-y (4 timesteps) gates completion count

__device__ __half g_wv_f16[(size_t)VOCAB * HID];   // fp16 weights
__device__ __half g_h_f16[(size_t)M_ROWS * HID];   // fp16 h (written by LSTM role)

// ---------------------------------------------------------------------------
// helpers
// ---------------------------------------------------------------------------
__device__ __forceinline__ uint32_t smem_u32(const void* p) {
    uint32_t a;
    asm("{ .reg .u64 t; cvta.to.shared.u64 t, %1; cvt.u32.u64 %0, t; }" : "=r"(a) : "l"(p));
    return a;
}
__device__ __forceinline__ void cp_async16(uint32_t dst, const void* src) {
    asm volatile("cp.async.cg.shared.global [%0], [%1], 16;" :: "r"(dst), "l"(src) : "memory");
}
#define CP_ASYNC_COMMIT() asm volatile("cp.async.commit_group;" ::: "memory")
#define CP_ASYNC_WAIT(n)  asm volatile("cp.async.wait_group %0;" :: "n"(n) : "memory")

#define BAR_VOCAB() asm volatile("bar.sync 1, 512;" ::: "memory")
#define BAR_LSTM()  asm volatile("bar.sync 2, 128;" ::: "memory")

__device__ __forceinline__ void ldsm_x4(uint32_t& r0, uint32_t& r1, uint32_t& r2, uint32_t& r3,
                                        uint32_t addr) {
    asm volatile("ldmatrix.sync.aligned.m8n8.x4.shared.b16 {%0,%1,%2,%3}, [%4];"
                 : "=r"(r0), "=r"(r1), "=r"(r2), "=r"(r3) : "r"(addr));
}
__device__ __forceinline__ void mma_f16(float* c, uint32_t a0, uint32_t a1, uint32_t a2, uint32_t a3,
                                        uint32_t b0, uint32_t b1) {
    asm volatile("mma.sync.aligned.m16n8k16.row.col.f32.f16.f16.f32 "
                 "{%0,%1,%2,%3}, {%4,%5,%6,%7}, {%8,%9}, {%0,%1,%2,%3};"
                 : "+f"(c[0]), "+f"(c[1]), "+f"(c[2]), "+f"(c[3])
                 : "r"(a0), "r"(a1), "r"(a2), "r"(a3), "r"(b0), "r"(b1));
}

__device__ __forceinline__ ull pack2(float x, float y) {
    ull r;
    asm("mov.b64 %0, {%1, %2};" : "=l"(r) : "r"(__float_as_uint(x)), "r"(__float_as_uint(y)));
    return r;
}
__device__ __forceinline__ void ffma2(ull& d, ull a, ull b) {
    asm("fma.rn.f32x2 %0, %1, %2, %3;" : "=l"(d) : "l"(a), "l"(b), "l"(d));
}
__device__ __forceinline__ float sum2(ull p) {
    return __uint_as_float((unsigned)p) + __uint_as_float((unsigned)(p >> 32));
}

// ---------------------------------------------------------------------------
// K0: prep + pool + counter reset
// ---------------------------------------------------------------------------
__global__ void prep_pool_kernel(const int* __restrict__ reports, const float* __restrict__ feat) {
    int i = blockIdx.x * blockDim.x + threadIdx.x;
    if (i == 0) { g_barrier = 0u; g_tile = 0; g_gtile = 0; }
    if (i < 25) g_xg_ready[i] = 0;
    if (i < M_ROWS) {
        int t = i >> 5, b = i & 31;
        g_tok[i] = (t == 0) ? 1 : reports[b * TT + (t - 1)];
    }
    if (i < BATCH * FEAT) {
        const float* p = feat + (size_t)i * 49;
        float s = 0.f;
        #pragma unroll
        for (int j = 0; j < 49; j++) s += p[j];
        g_pooled[i] = s * (1.f / 49.f);
    }
}

// ---------------------------------------------------------------------------
// K1: h0 + Wv fp16 convert
// ---------------------------------------------------------------------------
#define H0_BLOCKS 64
__global__ void h0_cvt_kernel(const float* __restrict__ fc_w, const float* __restrict__ fc_b,
                              const float* __restrict__ wv, __half* __restrict__ wv16) {
    if (blockIdx.x < H0_BLOCKS) {
        int i = blockIdx.x * blockDim.x + threadIdx.x;
        if (i >= BATCH * HID) return;
        int b = i >> 9, j = i & 511;
        const float* pw = fc_w + (size_t)j * FEAT;
        const float* pp = g_pooled + (size_t)b * FEAT;
        float acc = fc_b[j];
        #pragma unroll 4
        for (int k = 0; k < FEAT; k++) acc = fmaf(pw[k], pp[k], acc);
        g_hping[0][b * HID + j] = acc;
    } else {
        int i = (blockIdx.x - H0_BLOCKS) * blockDim.x + threadIdx.x;
        if (i >= VOCAB * HID / 4) return;
        float4 v = reinterpret_cast<const float4*>(wv)[i];
        reinterpret_cast<__half2*>(wv16)[i*2]   = __halves2half2(__float2half_rn(v.x), __float2half_rn(v.y));
        reinterpret_cast<__half2*>(wv16)[i*2+1] = __halves2half2(__float2half_rn(v.z), __float2half_rn(v.w));
    }
}

// ---------------------------------------------------------------------------
// K2: fused persistent kernel. 148 blocks x 640 threads (one wave).
//   warps 16-19 (tid 512+): LSTM on blocks 0..127 (waits on g_xg_ready per y)
//   warps  0-15: first drain the gates-tile queue (SIMT f32x2, writes g_xg,
//                publishes g_xg_ready), then the vocab mma tile queue.
// ---------------------------------------------------------------------------
#define WS_STRIDE 516
#define LSTM_SMEM_BYTES 101248
#define VG_STAGE 49152
#define FUSED_SMEM (LSTM_SMEM_BYTES + 2*VG_STAGE)   // 199552

__device__ __forceinline__ void lstm_role(float* sm, const float* __restrict__ Whh, int ltid) {
    float* ws  = sm;
    float* hs  = sm + 16*WS_STRIDE;
    float* gsm = sm + 16*WS_STRIDE + 32*WS_STRIDE;

    const int n0 = blockIdx.x * 4;

    for (int lr = 0; lr < 16; lr++) {
        int u = lr >> 2, g = lr & 3;
        const float* src = Whh + (size_t)(g * HID + n0 + u) * HID;
        for (int k = ltid; k < HID; k += 128) ws[lr * WS_STRIDE + k] = src[k];
    }

    const int rp = (ltid & 1) + ((ltid >> 5) << 1);
    const int r0 = rp * 2, r1 = r0 + 1;
    const int bp = (ltid >> 1) & 15;
    const int b0 = bp * 2, b1 = b0 + 1;
    const int cu = ltid >> 5;
    const int cb = ltid & 31;
    const int g0 = (r0 & 3) * HID + n0 + (r0 >> 2);
    const int g1 = (r1 & 3) * HID + n0 + (r1 >> 2);
    float c_reg = 0.f;

    BAR_LSTM();

    for (int t = 0; t < TT; t++) {
        // wait until this 4-step group's xg tile-row is complete
        if ((t & 3) == 0) {
            if (ltid == 0) {
                int yn = t >> 2;
                while (*((volatile int*)&g_xg_ready[yn]) < 16) { __nanosleep(64); }
            }
            BAR_LSTM();
            __threadfence();
        }

        const size_t xt = (size_t)t * BATCH * (4*HID);
        float x00 = __ldcg(&g_xg[xt + (size_t)b0 * (4*HID) + g0]);
        float x01 = __ldcg(&g_xg[xt + (size_t)b1 * (4*HID) + g0]);
        float x10 = __ldcg(&g_xg[xt + (size_t)b0 * (4*HID) + g1]);
        float x11 = __ldcg(&g_xg[xt + (size_t)b1 * (4*HID) + g1]);

        const float* hin = g_hping[t & 1];
        #pragma unroll 4
        for (int j = 0; j < 32; j++) {
            float4 v = __ldcg(reinterpret_cast<const float4*>(hin + j * HID + ltid * 4));
            *reinterpret_cast<float4*>(hs + j * WS_STRIDE + ltid * 4) = v;
        }
        BAR_LSTM();

        const ulonglong2* w0 = reinterpret_cast<const ulonglong2*>(ws + r0 * WS_STRIDE);
        const ulonglong2* w1 = reinterpret_cast<const ulonglong2*>(ws + r1 * WS_STRIDE);
        const ulonglong2* ha = reinterpret_cast<const ulonglong2*>(hs + b0 * WS_STRIDE);
        const ulonglong2* hb = reinterpret_cast<const ulonglong2*>(hs + b1 * WS_STRIDE);
        ull p00 = 0ull, p01 = 0ull, p10 = 0ull, p11 = 0ull;
        #pragma unroll 8
        for (int k = 0; k < HID/4; k++) {
            ulonglong2 wa = w0[k], wb = w1[k];
            ulonglong2 va = ha[k], vb = hb[k];
            ffma2(p00, wa.x, va.x); ffma2(p00, wa.y, va.y);
            ffma2(p01, wa.x, vb.x); ffma2(p01, wa.y, vb.y);
            ffma2(p10, wb.x, va.x); ffma2(p10, wb.y, va.y);
            ffma2(p11, wb.x, vb.x); ffma2(p11, wb.y, vb.y);
        }
        gsm[r0*33 + b0] = sum2(p00) + x00;
        gsm[r0*33 + b1] = sum2(p01) + x01;
        gsm[r1*33 + b0] = sum2(p10) + x10;
        gsm[r1*33 + b1] = sum2(p11) + x11;
        BAR_LSTM();

        {
            float iv = gsm[(cu*4 + 0)*33 + cb];
            float fv = gsm[(cu*4 + 1)*33 + cb];
            float gv = gsm[(cu*4 + 2)*33 + cb];
            float ov = gsm[(cu*4 + 3)*33 + cb];
            iv = 1.f / (1.f + __expf(-iv));
            fv = 1.f / (1.f + __expf(-fv));
            ov = 1.f / (1.f + __expf(-ov));
            gv = tanhf(gv);
            c_reg = fv * c_reg + iv * gv;
            float hn = ov * tanhf(c_reg);
            int nidx = n0 + cu;
            __stcg(&g_hping[(t + 1) & 1][cb * HID + nidx], hn);
            __stcg(reinterpret_cast<__half*>(&g_h_f16[((size_t)t * BATCH + cb) * HID + nidx]),
                   __float2half_rn(hn));
        }

        __threadfence();
        BAR_LSTM();
        if (ltid == 0) atomicAdd(&g_barrier, 1u);
        if (t + 1 < TT) {
            if (ltid == 0) {
                unsigned target = (unsigned)((t + 1) * NBLK_LSTM);
                while (*((volatile unsigned*)&g_barrier) < target) { __nanosleep(32); }
            }
            BAR_LSTM();
            __threadfence();
        }
    }
}

// ---- gates role (runs first on vocab warps): 512 threads, tile 128x128 K=256
// xg = gather(emb, tok) @ W_ih^T + b_ih + b_hh ; publishes g_xg_ready[y]
__device__ __forceinline__ void gates_role(float* As, const float* __restrict__ emb,
                                           const float* __restrict__ Wih,
                                           const float* __restrict__ b_ih,
                                           const float* __restrict__ b_hh, int tid) {
    __shared__ int s_gti;
    float* Bs = As + 16*132;
    const int ty = tid >> 5;        // 0..15 -> 8 rows
    const int tx = tid & 31;        // 0..31 -> 4 cols
    const int lr = tid >> 1;        // loader row 0..255 (A:0..127, reused for B)
    const int lkq = (tid & 1) * 8;  // loader k offset 0/8

    for (;;) {
        if (tid == 0) s_gti = atomicAdd(&g_gtile, 1);
        BAR_VOCAB();
        const int gi = s_gti;
        if (gi >= G_TILES) break;
        const int yy = gi >> 4;             // m-tile (ascending -> LSTM unblocks early)
        const int n0 = (gi & 15) * 128;
        const int m0 = yy * 128;

        ull acc[8][2];
        #pragma unroll
        for (int i = 0; i < 8; i++) { acc[i][0] = 0ull; acc[i][1] = 0ull; }

        const bool isA = tid < 256;
        const float* lrow;
        if (isA) lrow = emb + (size_t)g_tok[m0 + lr] * EMB;
        else     lrow = Wih + (size_t)(n0 + (lr - 128)) * EMB;
        const int srow = isA ? lr : (lr - 128);

        for (int k0 = 0; k0 < EMB; k0 += 16) {
            float4 v0 = __ldg(reinterpret_cast<const float4*>(lrow + k0 + lkq));
            float4 v1 = __ldg(reinterpret_cast<const float4*>(lrow + k0 + lkq + 4));
            BAR_VOCAB();
            float* dst = (isA ? As : Bs);
            dst[(lkq+0)*132 + srow] = v0.x; dst[(lkq+1)*132 + srow] = v0.y;
            dst[(lkq+2)*132 + srow] = v0.z; dst[(lkq+3)*132 + srow] = v0.w;
            dst[(lkq+4)*132 + srow] = v1.x; dst[(lkq+5)*132 + srow] = v1.y;
            dst[(lkq+6)*132 + srow] = v1.z; dst[(lkq+7)*132 + srow] = v1.w;
            BAR_VOCAB();

            #pragma unroll
            for (int kk = 0; kk < 16; kk++) {
                const float* ar = As + kk*132 + ty*8;
                const float* br = Bs + kk*132 + tx*4;
                float4 av0 = *reinterpret_cast<const float4*>(ar);
                float4 av1 = *reinterpret_cast<const float4*>(ar + 4);
                float4 bb  = *reinterpret_cast<const float4*>(br);
                ull bp0 = pack2(bb.x, bb.y);
                ull bp1 = pack2(bb.z, bb.w);
                float aa[8] = {av0.x, av0.y, av0.z, av0.w, av1.x, av1.y, av1.z, av1.w};
                #pragma unroll
                for (int i = 0; i < 8; i++) {
                    ull ap = pack2(aa[i], aa[i]);
                    ffma2(acc[i][0], ap, bp0);
                    ffma2(acc[i][1], ap, bp1);
                }
            }
            BAR_VOCAB();
        }

        // epilogue: xg[m][n] = acc + b_ih[n] + b_hh[n]
        float bias[4];
        #pragma unroll
        for (int j = 0; j < 4; j++) {
            int n = n0 + tx*4 + j;
            bias[j] = __ldg(b_ih + n) + __ldg(b_hh + n);
        }
        #pragma unroll
        for (int i = 0; i < 8; i++) {
            int m = m0 + ty*8 + i;
            float4 o;
            o.x = __uint_as_float((unsigned)(acc[i][0]))       + bias[0];
            o.y = __uint_as_float((unsigned)(acc[i][0] >> 32)) + bias[1];
            o.z = __uint_as_float((unsigned)(acc[i][1]))       + bias[2];
            o.w = __uint_as_float((unsigned)(acc[i][1] >> 32)) + bias[3];
            *reinterpret_cast<float4*>(g_xg + (size_t)m * (4*HID) + n0 + tx*4) = o;
        }
        __threadfence();
        BAR_VOCAB();
        if (tid == 0) atomicAdd(&g_xg_ready[yy], 1);
    }
}

// ---- vocab mma role (identical to R10): tiles 128x256, warp tile 32x64 ----
__device__ __forceinline__ void vocab_role(char* vsm_raw, const float* __restrict__ bv,
                                           float* __restrict__ out, int tid) {
    __shared__ int s_ti;
    const uint32_t smem = smem_u32(vsm_raw);
    const int wid  = tid >> 5;
    const int lane = tid & 31;
    const int wm   = wid >> 2;          // 0..3
    const int wn   = wid & 3;           // 0..3

    for (;;) {
        if (tid == 0) s_ti = atomicAdd(&g_tile, 1);
        BAR_VOCAB();
        const int ti = s_ti;
        if (ti >= N_TILES) break;
        const int yy = ti / 125;
        const int n0 = (ti - yy * 125) * 256;
        const int m0 = yy * 128;

        if (tid == 0) {
            unsigned need = (unsigned)((yy * 4 + 4) * NBLK_LSTM);
            while (*((volatile unsigned*)&g_barrier) < need) { __nanosleep(128); }
        }
        BAR_VOCAB();
        __threadfence();

        float acc[2][8][4];
        #pragma unroll
        for (int i = 0; i < 2; i++)
            #pragma unroll
            for (int j = 0; j < 8; j++)
                #pragma unroll
                for (int q = 0; q < 4; q++) acc[i][j][q] = 0.f;

        auto load_chunk = [&](int chunk) {
            const uint32_t stage = smem + (uint32_t)(chunk & 1) * VG_STAGE;
            const int kbase = chunk * 64;
            #pragma unroll
            for (int j = 0; j < 6; j++) {
                int i = tid + j * 512;          // 0..3071
                const __half* gb;
                int grow;
                uint32_t doff;
                int cc;
                if (i < 1024) {                  // A: 128 rows x 8 chunks
                    int r  = (i >> 3) & 127;
                    cc = i & 7;
                    gb = g_h_f16;
                    grow = m0 + r;
                    doff = (uint32_t)(r * 128) + (uint32_t)(((cc ^ (r & 7)) * 16));
                } else {                         // B: 256 rows x 8 chunks
                    int jj = i - 1024;
                    int r  = (jj >> 3) & 255;
                    cc = jj & 7;
                    gb = g_wv_f16;
                    grow = n0 + r;
                    doff = 16384u + (uint32_t)(r * 128) + (uint32_t)(((cc ^ (r & 7)) * 16));
                }
                cp_async16(stage + doff, gb + (size_t)grow * HID + kbase + cc * 8);
            }
            CP_ASYNC_COMMIT();
        };

        load_chunk(0);

        for (int chunk = 0; chunk < 8; chunk++) {
            if (chunk + 1 < 8) { load_chunk(chunk + 1); CP_ASYNC_WAIT(1); }
            else               { CP_ASYNC_WAIT(0); }
            BAR_VOCAB();

            const uint32_t stage = smem + (uint32_t)(chunk & 1) * VG_STAGE;
            const uint32_t aBase = stage;
            const uint32_t bBase = stage + 16384u;

            #pragma unroll
            for (int ks = 0; ks < 4; ks++) {
                uint32_t ah[2][4];
                #pragma unroll
                for (int mt = 0; mt < 2; mt++) {
                    int row = wm * 32 + mt * 16 + (lane & 7) + ((lane >> 3) & 1) * 8;
                    int ch  = ks * 2 + (lane >> 4);
                    uint32_t off = (uint32_t)(row * 128) + (uint32_t)((ch ^ (row & 7)) * 16);
                    ldsm_x4(ah[mt][0], ah[mt][1], ah[mt][2], ah[mt][3], aBase + off);
                }
                #pragma unroll
                for (int p = 0; p < 4; p++) {
                    int g   = lane >> 3;
                    int row = wn * 64 + p * 16 + (g & 1) * 8 + (lane & 7);
                    int ch  = ks * 2 + (g >> 1);
                    uint32_t off = (uint32_t)(row * 128) + (uint32_t)((ch ^ (row & 7)) * 16);
                    uint32_t bh[2][2];
                    {
                        uint32_t r0, r1, r2, r3;
                        ldsm_x4(r0, r1, r2, r3, bBase + off);
                        bh[0][0] = r0; bh[0][1] = r2;
                        bh[1][0] = r1; bh[1][1] = r3;
                    }
                    #pragma unroll
                    for (int mt = 0; mt < 2; mt++) {
                        #pragma unroll
                        for (int q = 0; q < 2; q++) {
                            int nt = p * 2 + q;
                            mma_f16(acc[mt][nt], ah[mt][0], ah[mt][1], ah[mt][2], ah[mt][3],
                                    bh[q][0], bh[q][1]);
                        }
                    }
                }
            }
            BAR_VOCAB();
        }

        #pragma unroll
        for (int mt = 0; mt < 2; mt++) {
            int gm0 = m0 + wm * 32 + mt * 16 + (lane >> 2);
            int gm1 = gm0 + 8;
            size_t ob0 = ((size_t)(gm0 & 31) * TT + (size_t)(gm0 >> 5)) * (size_t)VOCAB;
            size_t ob1 = ((size_t)(gm1 & 31) * TT + (size_t)(gm1 >> 5)) * (size_t)VOCAB;
            #pragma unroll
            for (int nt = 0; nt < 8; nt++) {
                int gn = n0 + wn * 64 + nt * 8 + (lane & 3) * 2;
                float bv0 = __ldg(bv + gn), bv1 = __ldg(bv + gn + 1);
                float2 v0 = make_float2(acc[mt][nt][0] + bv0, acc[mt][nt][1] + bv1);
                float2 v1 = make_float2(acc[mt][nt][2] + bv0, acc[mt][nt][3] + bv1);
                *reinterpret_cast<float2*>(out + ob0 + gn) = v0;
                *reinterpret_cast<float2*>(out + ob1 + gn) = v1;
            }
        }
    }
}

__global__ __launch_bounds__(640, 1)
void fused_kernel(const float* __restrict__ Whh, const float* __restrict__ bv,
                  float* __restrict__ out,
                  const float* __restrict__ emb, const float* __restrict__ Wih,
                  const float* __restrict__ b_ih, const float* __restrict__ b_hh)
{
    extern __shared__ char sm_raw[];
    const int tid = threadIdx.x;
    if (tid >= 512) {
        if (blockIdx.x < NBLK_LSTM)
            lstm_role(reinterpret_cast<float*>(sm_raw), Whh, tid - 512);
        return;
    }
    // vocab warps: gates GEMM first (fills g_xg, unblocks the LSTM), then vocab
    gates_role(reinterpret_cast<float*>(sm_raw + LSTM_SMEM_BYTES), emb, Wih, b_ih, b_hh, tid);
    vocab_role(sm_raw + LSTM_SMEM_BYTES, bv, out, tid);
}

// ---------------------------------------------------------------------------
// launch: K0 (prep+pool), K1 (h0+cvt), K2 (fused everything else)
// ---------------------------------------------------------------------------
extern "C" void kernel_launch(void* const* d_in, const int* in_sizes, int n_in,
                              void* d_out, int out_size) {
    const float* features  = (const float*)d_in[0];
    const int*   reports   = (const int*)  d_in[1];
    const float* emb_table = (const float*)d_in[2];
    const float* fc_w      = (const float*)d_in[3];
    const float* fc_b      = (const float*)d_in[4];
    const float* W_ih      = (const float*)d_in[5];
    const float* b_ih      = (const float*)d_in[6];
    const float* W_hh      = (const float*)d_in[7];
    const float* b_hh      = (const float*)d_in[8];
    const float* Wv        = (const float*)d_in[9];
    const float* bv        = (const float*)d_in[10];
    float* out = (float*)d_out;

    void *p_wv16 = nullptr;
    cudaGetSymbolAddress(&p_wv16, g_wv_f16);

    cudaFuncSetAttribute(fused_kernel, cudaFuncAttributeMaxDynamicSharedMemorySize, FUSED_SMEM);

    // K0: prep + pool + counters
    prep_pool_kernel<<<(BATCH * FEAT + 255) / 256, 256>>>(reports, features);
    // K1: h0 + Wv->fp16 convert
    {
        int cvt_blocks = (VOCAB * HID / 4 + 255) / 256;   // 16000
        h0_cvt_kernel<<<H0_BLOCKS + cvt_blocks, 256>>>(fc_w, fc_b, Wv, (__half*)p_wv16);
    }
    // K2: fused gates + LSTM + vocab (one wave of 148 blocks)
    fused_kernel<<<148, 640, FUSED_SMEM>>>(W_hh, bv, out, emb_table, W_ih, b_ih, b_hh);
}

// round 15
// speedup vs baseline: 1.3361x; 1.0245x over previous
#include <cuda_runtime.h>
#include <cuda_fp16.h>
#include <cstdint>
#include <cstddef>

#define VOCAB 32000
#define EMB   256
#define HID   512
#define FEAT  1024
#define BATCH 32
#define TT    100
#define M_ROWS (TT*BATCH)      // 3200
#define NBLK_LSTM 128
#define N_TILES (125*25)       // 3125 vocab tiles (128m x 256n)
#define G_TILES (16*25)        // 400 gates tiles (128m x 128n, K=256)
typedef unsigned long long ull;

// ---------------------------------------------------------------------------
// device scratch
// ---------------------------------------------------------------------------
__device__ float g_pooled[BATCH*FEAT];
__device__ float g_xg[(size_t)M_ROWS * 4 * HID];
__device__ float g_hping[2][BATCH*HID];
__device__ int   g_tok[M_ROWS];
__device__ unsigned g_barrier;
__device__ int   g_tile;
__device__ int   g_gtile;
__device__ int   g_xg_ready[25];

// chunked + pre-swizzled fp16 tensors for bulk-copy loading:
//   layout [kchunk(8)][row][128B], 16B unit cc stored at (cc ^ (row&7))
__device__ __half g_wv_c[(size_t)8 * VOCAB * 64];
__device__ __half g_h_c[(size_t)8 * M_ROWS * 64];

// ---------------------------------------------------------------------------
// helpers
// ---------------------------------------------------------------------------
__device__ __forceinline__ uint32_t smem_u32(const void* p) {
    uint32_t a;
    asm("{ .reg .u64 t; cvta.to.shared.u64 t, %1; cvt.u32.u64 %0, t; }" : "=r"(a) : "l"(p));
    return a;
}
#define BAR_VOCAB() asm volatile("bar.sync 1, 512;" ::: "memory")
#define BAR_LSTM()  asm volatile("bar.sync 2, 128;" ::: "memory")

#define MBARRIER_INIT(mb, cnt) \
    asm volatile("mbarrier.init.shared.b64 [%0], %1;" :: "r"((uint32_t)(mb)), "r"((uint32_t)(cnt)) : "memory")
#define MBARRIER_EXPECT_TX(mb, bytes) \
    asm volatile("mbarrier.arrive.expect_tx.shared.b64 _, [%0], %1;" :: "r"((uint32_t)(mb)), "r"((uint32_t)(bytes)) : "memory")
#define MBARRIER_WAIT_PARITY(mbar_smem_addr, phase_parity) do { \
    uint32_t _mbar = (uint32_t)(mbar_smem_addr); \
    uint32_t _parity = (uint32_t)(phase_parity); \
    uint32_t _done; \
    asm volatile("{\n\t.reg .pred p;\n\t" \
        "mbarrier.try_wait.parity.acquire.cta.shared::cta.b64 p, [%1], %2;\n\t" \
        "selp.b32 %0, 1, 0, p;\n\t}" : "=r"(_done) : "r"(_mbar), "r"(_parity) : "memory"); \
    if (!_done) { \
        asm volatile("{\n\t.reg .pred P1;\n\t" \
            "WAIT_LOOP_%=:\n\t" \
            "mbarrier.try_wait.parity.acquire.cta.shared::cta.b64 P1, [%0], %1, 0x989680;\n\t" \
            "@P1 bra.uni WAIT_DONE_%=;\n\t" \
            "bra.uni WAIT_LOOP_%=;\n\t" \
            "WAIT_DONE_%=:\n\t}" :: "r"(_mbar), "r"(_parity) : "memory"); \
    } \
} while(0)

__device__ __forceinline__ void bulk_g2s(uint32_t dst, const void* src, uint32_t bytes, uint32_t mb) {
    asm volatile("cp.async.bulk.shared::cta.global.mbarrier::complete_tx::bytes [%0], [%1], %2, [%3];"
                 :: "r"(dst), "l"(src), "r"(bytes), "r"(mb) : "memory");
}

__device__ __forceinline__ void ldsm_x4(uint32_t& r0, uint32_t& r1, uint32_t& r2, uint32_t& r3,
                                        uint32_t addr) {
    asm volatile("ldmatrix.sync.aligned.m8n8.x4.shared.b16 {%0,%1,%2,%3}, [%4];"
                 : "=r"(r0), "=r"(r1), "=r"(r2), "=r"(r3) : "r"(addr));
}
__device__ __forceinline__ void mma_f16(float* c, uint32_t a0, uint32_t a1, uint32_t a2, uint32_t a3,
                                        uint32_t b0, uint32_t b1) {
    asm volatile("mma.sync.aligned.m16n8k16.row.col.f32.f16.f16.f32 "
                 "{%0,%1,%2,%3}, {%4,%5,%6,%7}, {%8,%9}, {%0,%1,%2,%3};"
                 : "+f"(c[0]), "+f"(c[1]), "+f"(c[2]), "+f"(c[3])
                 : "r"(a0), "r"(a1), "r"(a2), "r"(a3), "r"(b0), "r"(b1));
}

__device__ __forceinline__ ull pack2(float x, float y) {
    ull r;
    asm("mov.b64 %0, {%1, %2};" : "=l"(r) : "r"(__float_as_uint(x)), "r"(__float_as_uint(y)));
    return r;
}
__device__ __forceinline__ void ffma2(ull& d, ull a, ull b) {
    asm("fma.rn.f32x2 %0, %1, %2, %3;" : "=l"(d) : "l"(a), "l"(b), "l"(d));
}
__device__ __forceinline__ float sum2(ull p) {
    return __uint_as_float((unsigned)p) + __uint_as_float((unsigned)(p >> 32));
}

// ---------------------------------------------------------------------------
// K0: prep + pool + counter reset
// ---------------------------------------------------------------------------
__global__ void prep_pool_kernel(const int* __restrict__ reports, const float* __restrict__ feat) {
    int i = blockIdx.x * blockDim.x + threadIdx.x;
    if (i == 0) { g_barrier = 0u; g_tile = 0; g_gtile = 0; }
    if (i < 25) g_xg_ready[i] = 0;
    if (i < M_ROWS) {
        int t = i >> 5, b = i & 31;
        g_tok[i] = (t == 0) ? 1 : reports[b * TT + (t - 1)];
    }
    if (i < BATCH * FEAT) {
        const float* p = feat + (size_t)i * 49;
        float s = 0.f;
        #pragma unroll
        for (int j = 0; j < 49; j++) s += p[j];
        g_pooled[i] = s * (1.f / 49.f);
    }
}

// ---------------------------------------------------------------------------
// K1: h0 + Wv fp16 convert into chunked/pre-swizzled layout
// cvt unit = 16B (8 halfs): (c, r, cc) -> g_wv_c[((c*VOCAB + r)*128) + (cc^(r&7))*16]
// ---------------------------------------------------------------------------
#define H0_BLOCKS 64
#define CVT_UNITS (8 * VOCAB * 8)     // 2,048,000
__global__ void h0_cvt_kernel(const float* __restrict__ fc_w, const float* __restrict__ fc_b,
                              const float* __restrict__ wv) {
    if (blockIdx.x < H0_BLOCKS) {
        int i = blockIdx.x * blockDim.x + threadIdx.x;
        if (i >= BATCH * HID) return;
        int b = i >> 9, j = i & 511;
        const float* pw = fc_w + (size_t)j * FEAT;
        const float* pp = g_pooled + (size_t)b * FEAT;
        float acc = fc_b[j];
        #pragma unroll 4
        for (int k = 0; k < FEAT; k++) acc = fmaf(pw[k], pp[k], acc);
        g_hping[0][b * HID + j] = acc;
    } else {
        int i = (blockIdx.x - H0_BLOCKS) * blockDim.x + threadIdx.x;
        if (i >= CVT_UNITS) return;
        int c   = i / (VOCAB * 8);
        int rem = i - c * (VOCAB * 8);
        int r   = rem >> 3;
        int cc  = rem & 7;
        const float* src = wv + (size_t)r * HID + c * 64 + cc * 8;
        float4 v0 = *reinterpret_cast<const float4*>(src);
        float4 v1 = *reinterpret_cast<const float4*>(src + 4);
        __half2 h0 = __floats2half2_rn(v0.x, v0.y);
        __half2 h1 = __floats2half2_rn(v0.z, v0.w);
        __half2 h2 = __floats2half2_rn(v1.x, v1.y);
        __half2 h3 = __floats2half2_rn(v1.z, v1.w);
        uint4 o;
        o.x = *reinterpret_cast<uint32_t*>(&h0);
        o.y = *reinterpret_cast<uint32_t*>(&h1);
        o.z = *reinterpret_cast<uint32_t*>(&h2);
        o.w = *reinterpret_cast<uint32_t*>(&h3);
        char* dst = reinterpret_cast<char*>(g_wv_c)
                  + ((size_t)c * VOCAB + (size_t)r) * 128 + (size_t)((cc ^ (r & 7)) * 16);
        *reinterpret_cast<uint4*>(dst) = o;
    }
}

// ---------------------------------------------------------------------------
// K2: fused persistent kernel. 148 blocks x 640 threads (one wave).
// ---------------------------------------------------------------------------
#define WS_STRIDE 516
#define LSTM_SMEM_BYTES 101248
#define VG_STAGE 49152
#define FUSED_SMEM (LSTM_SMEM_BYTES + 2*VG_STAGE)   // 199552

__device__ __forceinline__ void lstm_role(float* sm, const float* __restrict__ Whh, int ltid) {
    float* ws  = sm;
    float* hs  = sm + 16*WS_STRIDE;
    float* gsm = sm + 16*WS_STRIDE + 32*WS_STRIDE;

    const int n0 = blockIdx.x * 4;

    for (int lr = 0; lr < 16; lr++) {
        int u = lr >> 2, g = lr & 3;
        const float* src = Whh + (size_t)(g * HID + n0 + u) * HID;
        for (int k = ltid; k < HID; k += 128) ws[lr * WS_STRIDE + k] = src[k];
    }

    const int rp = (ltid & 1) + ((ltid >> 5) << 1);
    const int r0 = rp * 2, r1 = r0 + 1;
    const int bp = (ltid >> 1) & 15;
    const int b0 = bp * 2, b1 = b0 + 1;
    const int cu = ltid >> 5;
    const int cb = ltid & 31;
    const int g0 = (r0 & 3) * HID + n0 + (r0 >> 2);
    const int g1 = (r1 & 3) * HID + n0 + (r1 >> 2);
    float c_reg = 0.f;

    BAR_LSTM();

    for (int t = 0; t < TT; t++) {
        if ((t & 3) == 0) {
            if (ltid == 0) {
                int yn = t >> 2;
                while (*((volatile int*)&g_xg_ready[yn]) < 16) { __nanosleep(64); }
            }
            BAR_LSTM();
            __threadfence();
        }

        const size_t xt = (size_t)t * BATCH * (4*HID);
        float x00 = __ldcg(&g_xg[xt + (size_t)b0 * (4*HID) + g0]);
        float x01 = __ldcg(&g_xg[xt + (size_t)b1 * (4*HID) + g0]);
        float x10 = __ldcg(&g_xg[xt + (size_t)b0 * (4*HID) + g1]);
        float x11 = __ldcg(&g_xg[xt + (size_t)b1 * (4*HID) + g1]);

        const float* hin = g_hping[t & 1];
        #pragma unroll 4
        for (int j = 0; j < 32; j++) {
            float4 v = __ldcg(reinterpret_cast<const float4*>(hin + j * HID + ltid * 4));
            *reinterpret_cast<float4*>(hs + j * WS_STRIDE + ltid * 4) = v;
        }
        BAR_LSTM();

        const ulonglong2* w0 = reinterpret_cast<const ulonglong2*>(ws + r0 * WS_STRIDE);
        const ulonglong2* w1 = reinterpret_cast<const ulonglong2*>(ws + r1 * WS_STRIDE);
        const ulonglong2* ha = reinterpret_cast<const ulonglong2*>(hs + b0 * WS_STRIDE);
        const ulonglong2* hb = reinterpret_cast<const ulonglong2*>(hs + b1 * WS_STRIDE);
        ull p00 = 0ull, p01 = 0ull, p10 = 0ull, p11 = 0ull;
        #pragma unroll 8
        for (int k = 0; k < HID/4; k++) {
            ulonglong2 wa = w0[k], wb = w1[k];
            ulonglong2 va = ha[k], vb = hb[k];
            ffma2(p00, wa.x, va.x); ffma2(p00, wa.y, va.y);
            ffma2(p01, wa.x, vb.x); ffma2(p01, wa.y, vb.y);
            ffma2(p10, wb.x, va.x); ffma2(p10, wb.y, va.y);
            ffma2(p11, wb.x, vb.x); ffma2(p11, wb.y, vb.y);
        }
        gsm[r0*33 + b0] = sum2(p00) + x00;
        gsm[r0*33 + b1] = sum2(p01) + x01;
        gsm[r1*33 + b0] = sum2(p10) + x10;
        gsm[r1*33 + b1] = sum2(p11) + x11;
        BAR_LSTM();

        {
            float iv = gsm[(cu*4 + 0)*33 + cb];
            float fv = gsm[(cu*4 + 1)*33 + cb];
            float gv = gsm[(cu*4 + 2)*33 + cb];
            float ov = gsm[(cu*4 + 3)*33 + cb];
            iv = 1.f / (1.f + __expf(-iv));
            fv = 1.f / (1.f + __expf(-fv));
            ov = 1.f / (1.f + __expf(-ov));
            gv = tanhf(gv);
            c_reg = fv * c_reg + iv * gv;
            float hn = ov * tanhf(c_reg);
            int nidx = n0 + cu;
            __stcg(&g_hping[(t + 1) & 1][cb * HID + nidx], hn);
            // store h into chunked + swizzled fp16 layout (vocab A)
            int m  = t * BATCH + cb;
            int c  = nidx >> 6;
            int w  = nidx & 63;
            int cc = w >> 3;
            char* dst = reinterpret_cast<char*>(g_h_c)
                      + ((size_t)c * M_ROWS + (size_t)m) * 128
                      + (size_t)((cc ^ (m & 7)) * 16 + (w & 7) * 2);
            __stcg(reinterpret_cast<__half*>(dst), __float2half_rn(hn));
        }

        __threadfence();
        BAR_LSTM();
        if (ltid == 0) atomicAdd(&g_barrier, 1u);
        if (t + 1 < TT) {
            if (ltid == 0) {
                unsigned target = (unsigned)((t + 1) * NBLK_LSTM);
                while (*((volatile unsigned*)&g_barrier) < target) { __nanosleep(32); }
            }
            BAR_LSTM();
            __threadfence();
        }
    }
}

// ---- gates role (SIMT f32x2, fills g_xg, publishes g_xg_ready) ----
__device__ __forceinline__ void gates_role(float* As, const float* __restrict__ emb,
                                           const float* __restrict__ Wih,
                                           const float* __restrict__ b_ih,
                                           const float* __restrict__ b_hh, int tid) {
    __shared__ int s_gti;
    float* Bs = As + 16*132;
    const int ty = tid >> 5;
    const int tx = tid & 31;
    const int lr = tid >> 1;
    const int lkq = (tid & 1) * 8;

    for (;;) {
        if (tid == 0) s_gti = atomicAdd(&g_gtile, 1);
        BAR_VOCAB();
        const int gi = s_gti;
        if (gi >= G_TILES) break;
        const int yy = gi >> 4;
        const int n0 = (gi & 15) * 128;
        const int m0 = yy * 128;

        ull acc[8][2];
        #pragma unroll
        for (int i = 0; i < 8; i++) { acc[i][0] = 0ull; acc[i][1] = 0ull; }

        const bool isA = tid < 256;
        const float* lrow;
        if (isA) lrow = emb + (size_t)g_tok[m0 + lr] * EMB;
        else     lrow = Wih + (size_t)(n0 + (lr - 128)) * EMB;
        const int srow = isA ? lr : (lr - 128);

        for (int k0 = 0; k0 < EMB; k0 += 16) {
            float4 v0 = __ldg(reinterpret_cast<const float4*>(lrow + k0 + lkq));
            float4 v1 = __ldg(reinterpret_cast<const float4*>(lrow + k0 + lkq + 4));
            BAR_VOCAB();
            float* dst = (isA ? As : Bs);
            dst[(lkq+0)*132 + srow] = v0.x; dst[(lkq+1)*132 + srow] = v0.y;
            dst[(lkq+2)*132 + srow] = v0.z; dst[(lkq+3)*132 + srow] = v0.w;
            dst[(lkq+4)*132 + srow] = v1.x; dst[(lkq+5)*132 + srow] = v1.y;
            dst[(lkq+6)*132 + srow] = v1.z; dst[(lkq+7)*132 + srow] = v1.w;
            BAR_VOCAB();

            #pragma unroll
            for (int kk = 0; kk < 16; kk++) {
                const float* ar = As + kk*132 + ty*8;
                const float* br = Bs + kk*132 + tx*4;
                float4 av0 = *reinterpret_cast<const float4*>(ar);
                float4 av1 = *reinterpret_cast<const float4*>(ar + 4);
                float4 bb  = *reinterpret_cast<const float4*>(br);
                ull bp0 = pack2(bb.x, bb.y);
                ull bp1 = pack2(bb.z, bb.w);
                float aa[8] = {av0.x, av0.y, av0.z, av0.w, av1.x, av1.y, av1.z, av1.w};
                #pragma unroll
                for (int i = 0; i < 8; i++) {
                    ull ap = pack2(aa[i], aa[i]);
                    ffma2(acc[i][0], ap, bp0);
                    ffma2(acc[i][1], ap, bp1);
                }
            }
            BAR_VOCAB();
        }

        float bias[4];
        #pragma unroll
        for (int j = 0; j < 4; j++) {
            int n = n0 + tx*4 + j;
            bias[j] = __ldg(b_ih + n) + __ldg(b_hh + n);
        }
        #pragma unroll
        for (int i = 0; i < 8; i++) {
            int m = m0 + ty*8 + i;
            float4 o;
            o.x = __uint_as_float((unsigned)(acc[i][0]))       + bias[0];
            o.y = __uint_as_float((unsigned)(acc[i][0] >> 32)) + bias[1];
            o.z = __uint_as_float((unsigned)(acc[i][1]))       + bias[2];
            o.w = __uint_as_float((unsigned)(acc[i][1] >> 32)) + bias[3];
            *reinterpret_cast<float4*>(g_xg + (size_t)m * (4*HID) + n0 + tx*4) = o;
        }
        __threadfence();
        BAR_VOCAB();
        if (tid == 0) atomicAdd(&g_xg_ready[yy], 1);
    }
}

// ---- vocab mma role: tiles 128x256, warp tile 32x64, bulk-copy loading ----
__device__ __forceinline__ void vocab_role(char* vsm_raw, const float* __restrict__ bv,
                                           float* __restrict__ out, int tid,
                                           uint32_t mb0, uint32_t mb1) {
    __shared__ int s_ti;
    const uint32_t smem = smem_u32(vsm_raw);
    const int wid  = tid >> 5;
    const int lane = tid & 31;
    const int wm   = wid >> 2;
    const int wn   = wid & 3;
    int ph0 = 0, ph1 = 0;

    for (;;) {
        if (tid == 0) s_ti = atomicAdd(&g_tile, 1);
        BAR_VOCAB();
        const int ti = s_ti;
        if (ti >= N_TILES) break;
        const int yy = ti / 125;
        const int n0 = (ti - yy * 125) * 256;
        const int m0 = yy * 128;

        if (tid == 0) {
            unsigned need = (unsigned)((yy * 4 + 4) * NBLK_LSTM);
            while (*((volatile unsigned*)&g_barrier) < need) { __nanosleep(128); }
        }
        BAR_VOCAB();
        __threadfence();

        float acc[2][8][4];
        #pragma unroll
        for (int i = 0; i < 2; i++)
            #pragma unroll
            for (int j = 0; j < 8; j++)
                #pragma unroll
                for (int q = 0; q < 4; q++) acc[i][j][q] = 0.f;

        // bulk issue: one thread, two copies per chunk (A 16KB, B 32KB)
        auto issue = [&](int chunk) {
            if (tid == 0) {
                const int s = chunk & 1;
                const uint32_t mb = s ? mb1 : mb0;
                const uint32_t stage = smem + (uint32_t)s * VG_STAGE;
                MBARRIER_EXPECT_TX(mb, 49152u);
                const char* asrc = reinterpret_cast<const char*>(g_h_c)
                                 + (size_t)chunk * ((size_t)M_ROWS * 128) + (size_t)m0 * 128;
                const char* bsrc = reinterpret_cast<const char*>(g_wv_c)
                                 + (size_t)chunk * ((size_t)VOCAB * 128) + (size_t)n0 * 128;
                bulk_g2s(stage, asrc, 16384u, mb);
                bulk_g2s(stage + 16384u, bsrc, 32768u, mb);
            }
        };

        issue(0);

        for (int chunk = 0; chunk < 8; chunk++) {
            if (chunk + 1 < 8) issue(chunk + 1);
            // wait for this chunk's stage
            if (chunk & 1) { MBARRIER_WAIT_PARITY(mb1, ph1); ph1 ^= 1; }
            else           { MBARRIER_WAIT_PARITY(mb0, ph0); ph0 ^= 1; }

            const uint32_t stage = smem + (uint32_t)(chunk & 1) * VG_STAGE;
            const uint32_t aBase = stage;
            const uint32_t bBase = stage + 16384u;

            #pragma unroll
            for (int ks = 0; ks < 4; ks++) {
                uint32_t ah[2][4];
                #pragma unroll
                for (int mt = 0; mt < 2; mt++) {
                    int row = wm * 32 + mt * 16 + (lane & 7) + ((lane >> 3) & 1) * 8;
                    int ch  = ks * 2 + (lane >> 4);
                    uint32_t off = (uint32_t)(row * 128) + (uint32_t)((ch ^ (row & 7)) * 16);
                    ldsm_x4(ah[mt][0], ah[mt][1], ah[mt][2], ah[mt][3], aBase + off);
                }
                #pragma unroll
                for (int p = 0; p < 4; p++) {
                    int g   = lane >> 3;
                    int row = wn * 64 + p * 16 + (g & 1) * 8 + (lane & 7);
                    int ch  = ks * 2 + (g >> 1);
                    uint32_t off = (uint32_t)(row * 128) + (uint32_t)((ch ^ (row & 7)) * 16);
                    uint32_t bh[2][2];
                    {
                        uint32_t r0, r1, r2, r3;
                        ldsm_x4(r0, r1, r2, r3, bBase + off);
                        bh[0][0] = r0; bh[0][1] = r2;
                        bh[1][0] = r1; bh[1][1] = r3;
                    }
                    #pragma unroll
                    for (int mt = 0; mt < 2; mt++) {
                        #pragma unroll
                        for (int q = 0; q < 2; q++) {
                            int nt = p * 2 + q;
                            mma_f16(acc[mt][nt], ah[mt][0], ah[mt][1], ah[mt][2], ah[mt][3],
                                    bh[q][0], bh[q][1]);
                        }
                    }
                }
            }
            BAR_VOCAB();   // all warps done with this stage before tid0 refills it
        }

        #pragma unroll
        for (int mt = 0; mt < 2; mt++) {
            int gm0 = m0 + wm * 32 + mt * 16 + (lane >> 2);
            int gm1 = gm0 + 8;
            size_t ob0 = ((size_t)(gm0 & 31) * TT + (size_t)(gm0 >> 5)) * (size_t)VOCAB;
            size_t ob1 = ((size_t)(gm1 & 31) * TT + (size_t)(gm1 >> 5)) * (size_t)VOCAB;
            #pragma unroll
            for (int nt = 0; nt < 8; nt++) {
                int gn = n0 + wn * 64 + nt * 8 + (lane & 3) * 2;
                float bv0 = __ldg(bv + gn), bv1 = __ldg(bv + gn + 1);
                float2 v0 = make_float2(acc[mt][nt][0] + bv0, acc[mt][nt][1] + bv1);
                float2 v1 = make_float2(acc[mt][nt][2] + bv0, acc[mt][nt][3] + bv1);
                *reinterpret_cast<float2*>(out + ob0 + gn) = v0;
                *reinterpret_cast<float2*>(out + ob1 + gn) = v1;
            }
        }
    }
}

__global__ __launch_bounds__(640, 1)
void fused_kernel(const float* __restrict__ Whh, const float* __restrict__ bv,
                  float* __restrict__ out,
                  const float* __restrict__ emb, const float* __restrict__ Wih,
                  const float* __restrict__ b_ih, const float* __restrict__ b_hh)
{
    extern __shared__ char sm_raw[];
    __shared__ uint64_t s_mbar[2];
    const int tid = threadIdx.x;
    if (tid >= 512) {
        if (blockIdx.x < NBLK_LSTM)
            lstm_role(reinterpret_cast<float*>(sm_raw), Whh, tid - 512);
        return;
    }
    const uint32_t mb0 = smem_u32(&s_mbar[0]);
    const uint32_t mb1 = smem_u32(&s_mbar[1]);
    if (tid == 0) {
        MBARRIER_INIT(mb0, 1);
        MBARRIER_INIT(mb1, 1);
    }
    BAR_VOCAB();
    gates_role(reinterpret_cast<float*>(sm_raw + LSTM_SMEM_BYTES), emb, Wih, b_ih, b_hh, tid);
    vocab_role(sm_raw + LSTM_SMEM_BYTES, bv, out, tid, mb0, mb1);
}

// ---------------------------------------------------------------------------
// launch
// ---------------------------------------------------------------------------
extern "C" void kernel_launch(void* const* d_in, const int* in_sizes, int n_in,
                              void* d_out, int out_size) {
    const float* features  = (const float*)d_in[0];
    const int*   reports   = (const int*)  d_in[1];
    const float* emb_table = (const float*)d_in[2];
    const float* fc_w      = (const float*)d_in[3];
    const float* fc_b      = (const float*)d_in[4];
    const float* W_ih      = (const float*)d_in[5];
    const float* b_ih      = (const float*)d_in[6];
    const float* W_hh      = (const float*)d_in[7];
    const float* b_hh      = (const float*)d_in[8];
    const float* Wv        = (const float*)d_in[9];
    const float* bv        = (const float*)d_in[10];
    float* out = (float*)d_out;

    cudaFuncSetAttribute(fused_kernel, cudaFuncAttributeMaxDynamicSharedMemorySize, FUSED_SMEM);

    // K0: prep + pool + counters
    prep_pool_kernel<<<(BATCH * FEAT + 255) / 256, 256>>>(reports, features);
    // K1: h0 + Wv -> chunked/swizzled fp16
    {
        int cvt_blocks = (CVT_UNITS + 255) / 256;   // 8000
        h0_cvt_kernel<<<H0_BLOCKS + cvt_blocks, 256>>>(fc_w, fc_b, Wv);
    }
    // K2: fused gates + LSTM + vocab (one wave of 148 blocks)
    fused_kernel<<<148, 640, FUSED_SMEM>>>(W_hh, bv, out, emb_table, W_ih, b_ih, b_hh);
}

// round 16
// speedup vs baseline: 1.5090x; 1.1294x over previous
#include <cuda_runtime.h>
#include <cuda_fp16.h>
#include <cstdint>
#include <cstddef>

#define VOCAB 32000
#define EMB   256
#define HID   512
#define FEAT  1024
#define BATCH 32
#define TT    100
#define M_ROWS (TT*BATCH)      // 3200
#define NBLK_LSTM 128
#define NBLK 148
#define N_TILES (125*25)       // 3125 vocab tiles (128m x 256n)
#define G_TILES (16*25)        // 400 gates tiles (128m x 128n, K=256)
typedef unsigned long long ull;

// ---------------------------------------------------------------------------
// device scratch
// ---------------------------------------------------------------------------
__device__ float g_pooled[BATCH*FEAT];
__device__ float g_xg[(size_t)M_ROWS * 4 * HID];
__device__ float g_hping[2][BATCH*HID];
__device__ int   g_tok[M_ROWS];
__device__ unsigned g_barrier;
__device__ int   g_tile;
__device__ int   g_gtile;
__device__ int   g_cvtdone;
__device__ int   g_xg_ready[25];

// chunked + pre-swizzled fp16 tensors for bulk-copy loading:
//   layout [kchunk(8)][row][128B], 16B unit cc stored at (cc ^ (row&7))
__device__ __half g_wv_c[(size_t)8 * VOCAB * 64];
__device__ __half g_h_c[(size_t)8 * M_ROWS * 64];

// ---------------------------------------------------------------------------
// helpers
// ---------------------------------------------------------------------------
__device__ __forceinline__ uint32_t smem_u32(const void* p) {
    uint32_t a;
    asm("{ .reg .u64 t; cvta.to.shared.u64 t, %1; cvt.u32.u64 %0, t; }" : "=r"(a) : "l"(p));
    return a;
}
#define BAR_VOCAB() asm volatile("bar.sync 1, 512;" ::: "memory")
#define BAR_LSTM()  asm volatile("bar.sync 2, 128;" ::: "memory")

#define MBARRIER_INIT(mb, cnt) \
    asm volatile("mbarrier.init.shared.b64 [%0], %1;" :: "r"((uint32_t)(mb)), "r"((uint32_t)(cnt)) : "memory")
#define MBARRIER_EXPECT_TX(mb, bytes) \
    asm volatile("mbarrier.arrive.expect_tx.shared.b64 _, [%0], %1;" :: "r"((uint32_t)(mb)), "r"((uint32_t)(bytes)) : "memory")
#define MBARRIER_WAIT_PARITY(mbar_smem_addr, phase_parity) do { \
    uint32_t _mbar = (uint32_t)(mbar_smem_addr); \
    uint32_t _parity = (uint32_t)(phase_parity); \
    uint32_t _done; \
    asm volatile("{\n\t.reg .pred p;\n\t" \
        "mbarrier.try_wait.parity.acquire.cta.shared::cta.b64 p, [%1], %2;\n\t" \
        "selp.b32 %0, 1, 0, p;\n\t}" : "=r"(_done) : "r"(_mbar), "r"(_parity) : "memory"); \
    if (!_done) { \
        asm volatile("{\n\t.reg .pred P1;\n\t" \
            "WAIT_LOOP_%=:\n\t" \
            "mbarrier.try_wait.parity.acquire.cta.shared::cta.b64 P1, [%0], %1, 0x989680;\n\t" \
            "@P1 bra.uni WAIT_DONE_%=;\n\t" \
            "bra.uni WAIT_LOOP_%=;\n\t" \
            "WAIT_DONE_%=:\n\t}" :: "r"(_mbar), "r"(_parity) : "memory"); \
    } \
} while(0)

__device__ __forceinline__ void bulk_g2s(uint32_t dst, const void* src, uint32_t bytes, uint32_t mb) {
    asm volatile("cp.async.bulk.shared::cta.global.mbarrier::complete_tx::bytes [%0], [%1], %2, [%3];"
                 :: "r"(dst), "l"(src), "r"(bytes), "r"(mb) : "memory");
}

__device__ __forceinline__ void ldsm_x4(uint32_t& r0, uint32_t& r1, uint32_t& r2, uint32_t& r3,
                                        uint32_t addr) {
    asm volatile("ldmatrix.sync.aligned.m8n8.x4.shared.b16 {%0,%1,%2,%3}, [%4];"
                 : "=r"(r0), "=r"(r1), "=r"(r2), "=r"(r3) : "r"(addr));
}
__device__ __forceinline__ void mma_f16(float* c, uint32_t a0, uint32_t a1, uint32_t a2, uint32_t a3,
                                        uint32_t b0, uint32_t b1) {
    asm volatile("mma.sync.aligned.m16n8k16.row.col.f32.f16.f16.f32 "
                 "{%0,%1,%2,%3}, {%4,%5,%6,%7}, {%8,%9}, {%0,%1,%2,%3};"
                 : "+f"(c[0]), "+f"(c[1]), "+f"(c[2]), "+f"(c[3])
                 : "r"(a0), "r"(a1), "r"(a2), "r"(a3), "r"(b0), "r"(b1));
}

__device__ __forceinline__ ull pack2(float x, float y) {
    ull r;
    asm("mov.b64 %0, {%1, %2};" : "=l"(r) : "r"(__float_as_uint(x)), "r"(__float_as_uint(y)));
    return r;
}
__device__ __forceinline__ void ffma2(ull& d, ull a, ull b) {
    asm("fma.rn.f32x2 %0, %1, %2, %3;" : "=l"(d) : "l"(a), "l"(b), "l"(d));
}
__device__ __forceinline__ float sum2(ull p) {
    return __uint_as_float((unsigned)p) + __uint_as_float((unsigned)(p >> 32));
}

// ---------------------------------------------------------------------------
// K0: prep + pool + counter reset (runs every launch -> graph-replay safe)
// ---------------------------------------------------------------------------
__global__ void prep_pool_kernel(const int* __restrict__ reports, const float* __restrict__ feat) {
    int i = blockIdx.x * blockDim.x + threadIdx.x;
    if (i == 0) { g_barrier = 0u; g_tile = 0; g_gtile = 0; g_cvtdone = 0; }
    if (i < 25) g_xg_ready[i] = 0;
    if (i < M_ROWS) {
        int t = i >> 5, b = i & 31;
        g_tok[i] = (t == 0) ? 1 : reports[b * TT + (t - 1)];
    }
    if (i < BATCH * FEAT) {
        const float* p = feat + (size_t)i * 49;
        float s = 0.f;
        #pragma unroll
        for (int j = 0; j < 49; j++) s += p[j];
        g_pooled[i] = s * (1.f / 49.f);
    }
}

// ---------------------------------------------------------------------------
// K1: fused persistent kernel. 148 blocks x 640 threads (one wave).
//   warps 16-19 (blocks<128): h0 slice -> LSTM (g_barrier shifted by +128)
//   warps  0-15: Wv cvt (grid-stride) -> gates queue -> vocab mma queue
// ---------------------------------------------------------------------------
#define WS_STRIDE 516
#define LSTM_SMEM_BYTES 101248
#define VG_STAGE 49152
#define FUSED_SMEM (LSTM_SMEM_BYTES + 2*VG_STAGE)   // 199552
#define CVT_UNITS (8 * VOCAB * 8)     // 2,048,000

__device__ __forceinline__ void lstm_role(float* sm, const float* __restrict__ Whh,
                                          const float* __restrict__ fc_w,
                                          const float* __restrict__ fc_b, int ltid) {
    float* ws  = sm;
    float* hs  = sm + 16*WS_STRIDE;
    float* gsm = sm + 16*WS_STRIDE + 32*WS_STRIDE;

    const int n0 = blockIdx.x * 4;

    // ---- h0 slice: thread -> (b = ltid&31, unit u = ltid>>5) ----
    {
        int b = ltid & 31, u = ltid >> 5;
        int j = n0 + u;
        const float4* pw = reinterpret_cast<const float4*>(fc_w + (size_t)j * FEAT);
        const float4* pp = reinterpret_cast<const float4*>(g_pooled + (size_t)b * FEAT);
        float acc = fc_b[j];
        #pragma unroll 4
        for (int k = 0; k < FEAT/4; k++) {
            float4 w = pw[k], p = pp[k];
            acc = fmaf(w.x, p.x, acc);
            acc = fmaf(w.y, p.y, acc);
            acc = fmaf(w.z, p.z, acc);
            acc = fmaf(w.w, p.w, acc);
        }
        __stcg(&g_hping[0][b * HID + j], acc);
    }

    // ---- cache W_hh slice ----
    for (int lr = 0; lr < 16; lr++) {
        int u = lr >> 2, g = lr & 3;
        const float* src = Whh + (size_t)(g * HID + n0 + u) * HID;
        for (int k = ltid; k < HID; k += 128) ws[lr * WS_STRIDE + k] = src[k];
    }

    // publish h0 slice; wait for all 128 blocks' h0
    __threadfence();
    BAR_LSTM();
    if (ltid == 0) {
        atomicAdd(&g_barrier, 1u);
        while (*((volatile unsigned*)&g_barrier) < (unsigned)NBLK_LSTM) { __nanosleep(64); }
    }
    BAR_LSTM();
    __threadfence();

    const int rp = (ltid & 1) + ((ltid >> 5) << 1);
    const int r0 = rp * 2, r1 = r0 + 1;
    const int bp = (ltid >> 1) & 15;
    const int b0 = bp * 2, b1 = b0 + 1;
    const int cu = ltid >> 5;
    const int cb = ltid & 31;
    const int g0 = (r0 & 3) * HID + n0 + (r0 >> 2);
    const int g1 = (r1 & 3) * HID + n0 + (r1 >> 2);
    float c_reg = 0.f;

    for (int t = 0; t < TT; t++) {
        if ((t & 3) == 0) {
            if (ltid == 0) {
                int yn = t >> 2;
                while (*((volatile int*)&g_xg_ready[yn]) < 16) { __nanosleep(64); }
            }
            BAR_LSTM();
            __threadfence();
        }

        const size_t xt = (size_t)t * BATCH * (4*HID);
        float x00 = __ldcg(&g_xg[xt + (size_t)b0 * (4*HID) + g0]);
        float x01 = __ldcg(&g_xg[xt + (size_t)b1 * (4*HID) + g0]);
        float x10 = __ldcg(&g_xg[xt + (size_t)b0 * (4*HID) + g1]);
        float x11 = __ldcg(&g_xg[xt + (size_t)b1 * (4*HID) + g1]);

        const float* hin = g_hping[t & 1];
        #pragma unroll 4
        for (int j = 0; j < 32; j++) {
            float4 v = __ldcg(reinterpret_cast<const float4*>(hin + j * HID + ltid * 4));
            *reinterpret_cast<float4*>(hs + j * WS_STRIDE + ltid * 4) = v;
        }
        BAR_LSTM();

        const ulonglong2* w0 = reinterpret_cast<const ulonglong2*>(ws + r0 * WS_STRIDE);
        const ulonglong2* w1 = reinterpret_cast<const ulonglong2*>(ws + r1 * WS_STRIDE);
        const ulonglong2* ha = reinterpret_cast<const ulonglong2*>(hs + b0 * WS_STRIDE);
        const ulonglong2* hb = reinterpret_cast<const ulonglong2*>(hs + b1 * WS_STRIDE);
        ull p00 = 0ull, p01 = 0ull, p10 = 0ull, p11 = 0ull;
        #pragma unroll 8
        for (int k = 0; k < HID/4; k++) {
            ulonglong2 wa = w0[k], wb = w1[k];
            ulonglong2 va = ha[k], vb = hb[k];
            ffma2(p00, wa.x, va.x); ffma2(p00, wa.y, va.y);
            ffma2(p01, wa.x, vb.x); ffma2(p01, wa.y, vb.y);
            ffma2(p10, wb.x, va.x); ffma2(p10, wb.y, va.y);
            ffma2(p11, wb.x, vb.x); ffma2(p11, wb.y, vb.y);
        }
        gsm[r0*33 + b0] = sum2(p00) + x00;
        gsm[r0*33 + b1] = sum2(p01) + x01;
        gsm[r1*33 + b0] = sum2(p10) + x10;
        gsm[r1*33 + b1] = sum2(p11) + x11;
        BAR_LSTM();

        {
            float iv = gsm[(cu*4 + 0)*33 + cb];
            float fv = gsm[(cu*4 + 1)*33 + cb];
            float gv = gsm[(cu*4 + 2)*33 + cb];
            float ov = gsm[(cu*4 + 3)*33 + cb];
            iv = 1.f / (1.f + __expf(-iv));
            fv = 1.f / (1.f + __expf(-fv));
            ov = 1.f / (1.f + __expf(-ov));
            gv = tanhf(gv);
            c_reg = fv * c_reg + iv * gv;
            float hn = ov * tanhf(c_reg);
            int nidx = n0 + cu;
            __stcg(&g_hping[(t + 1) & 1][cb * HID + nidx], hn);
            int m  = t * BATCH + cb;
            int c  = nidx >> 6;
            int w  = nidx & 63;
            int cc = w >> 3;
            char* dst = reinterpret_cast<char*>(g_h_c)
                      + ((size_t)c * M_ROWS + (size_t)m) * 128
                      + (size_t)((cc ^ (m & 7)) * 16 + (w & 7) * 2);
            __stcg(reinterpret_cast<__half*>(dst), __float2half_rn(hn));
        }

        __threadfence();
        BAR_LSTM();
        if (ltid == 0) atomicAdd(&g_barrier, 1u);
        if (t + 1 < TT) {
            if (ltid == 0) {
                unsigned target = (unsigned)((t + 2) * NBLK_LSTM);   // +128 h0 arrivals
                while (*((volatile unsigned*)&g_barrier) < target) { __nanosleep(32); }
            }
            BAR_LSTM();
            __threadfence();
        }
    }
}

// ---- cvt phase (vocab warps, grid-stride): Wv -> chunked/swizzled fp16 ----
__device__ __forceinline__ void cvt_phase(const float* __restrict__ wv, int tid) {
    const int stride = NBLK * 512;
    for (int i = blockIdx.x * 512 + tid; i < CVT_UNITS; i += stride) {
        int c   = i / (VOCAB * 8);
        int rem = i - c * (VOCAB * 8);
        int r   = rem >> 3;
        int cc  = rem & 7;
        const float* src = wv + (size_t)r * HID + c * 64 + cc * 8;
        float4 v0 = *reinterpret_cast<const float4*>(src);
        float4 v1 = *reinterpret_cast<const float4*>(src + 4);
        __half2 h0 = __floats2half2_rn(v0.x, v0.y);
        __half2 h1 = __floats2half2_rn(v0.z, v0.w);
        __half2 h2 = __floats2half2_rn(v1.x, v1.y);
        __half2 h3 = __floats2half2_rn(v1.z, v1.w);
        uint4 o;
        o.x = *reinterpret_cast<uint32_t*>(&h0);
        o.y = *reinterpret_cast<uint32_t*>(&h1);
        o.z = *reinterpret_cast<uint32_t*>(&h2);
        o.w = *reinterpret_cast<uint32_t*>(&h3);
        char* dst = reinterpret_cast<char*>(g_wv_c)
                  + ((size_t)c * VOCAB + (size_t)r) * 128 + (size_t)((cc ^ (r & 7)) * 16);
        *reinterpret_cast<uint4*>(dst) = o;
    }
    __threadfence();
    BAR_VOCAB();
    if (tid == 0) atomicAdd(&g_cvtdone, 1);
}

// ---- gates role (SIMT f32x2, fills g_xg, publishes g_xg_ready) ----
__device__ __forceinline__ void gates_role(float* As, const float* __restrict__ emb,
                                           const float* __restrict__ Wih,
                                           const float* __restrict__ b_ih,
                                           const float* __restrict__ b_hh, int tid) {
    __shared__ int s_gti;
    float* Bs = As + 16*132;
    const int ty = tid >> 5;
    const int tx = tid & 31;
    const int lr = tid >> 1;
    const int lkq = (tid & 1) * 8;

    for (;;) {
        if (tid == 0) s_gti = atomicAdd(&g_gtile, 1);
        BAR_VOCAB();
        const int gi = s_gti;
        if (gi >= G_TILES) break;
        const int yy = gi >> 4;
        const int n0 = (gi & 15) * 128;
        const int m0 = yy * 128;

        ull acc[8][2];
        #pragma unroll
        for (int i = 0; i < 8; i++) { acc[i][0] = 0ull; acc[i][1] = 0ull; }

        const bool isA = tid < 256;
        const float* lrow;
        if (isA) lrow = emb + (size_t)g_tok[m0 + lr] * EMB;
        else     lrow = Wih + (size_t)(n0 + (lr - 128)) * EMB;
        const int srow = isA ? lr : (lr - 128);

        for (int k0 = 0; k0 < EMB; k0 += 16) {
            float4 v0 = __ldg(reinterpret_cast<const float4*>(lrow + k0 + lkq));
            float4 v1 = __ldg(reinterpret_cast<const float4*>(lrow + k0 + lkq + 4));
            BAR_VOCAB();
            float* dst = (isA ? As : Bs);
            dst[(lkq+0)*132 + srow] = v0.x; dst[(lkq+1)*132 + srow] = v0.y;
            dst[(lkq+2)*132 + srow] = v0.z; dst[(lkq+3)*132 + srow] = v0.w;
            dst[(lkq+4)*132 + srow] = v1.x; dst[(lkq+5)*132 + srow] = v1.y;
            dst[(lkq+6)*132 + srow] = v1.z; dst[(lkq+7)*132 + srow] = v1.w;
            BAR_VOCAB();

            #pragma unroll
            for (int kk = 0; kk < 16; kk++) {
                const float* ar = As + kk*132 + ty*8;
                const float* br = Bs + kk*132 + tx*4;
                float4 av0 = *reinterpret_cast<const float4*>(ar);
                float4 av1 = *reinterpret_cast<const float4*>(ar + 4);
                float4 bb  = *reinterpret_cast<const float4*>(br);
                ull bp0 = pack2(bb.x, bb.y);
                ull bp1 = pack2(bb.z, bb.w);
                float aa[8] = {av0.x, av0.y, av0.z, av0.w, av1.x, av1.y, av1.z, av1.w};
                #pragma unroll
                for (int i = 0; i < 8; i++) {
                    ull ap = pack2(aa[i], aa[i]);
                    ffma2(acc[i][0], ap, bp0);
                    ffma2(acc[i][1], ap, bp1);
                }
            }
            BAR_VOCAB();
        }

        float bias[4];
        #pragma unroll
        for (int j = 0; j < 4; j++) {
            int n = n0 + tx*4 + j;
            bias[j] = __ldg(b_ih + n) + __ldg(b_hh + n);
        }
        #pragma unroll
        for (int i = 0; i < 8; i++) {
            int m = m0 + ty*8 + i;
            float4 o;
            o.x = __uint_as_float((unsigned)(acc[i][0]))       + bias[0];
            o.y = __uint_as_float((unsigned)(acc[i][0] >> 32)) + bias[1];
            o.z = __uint_as_float((unsigned)(acc[i][1]))       + bias[2];
            o.w = __uint_as_float((unsigned)(acc[i][1] >> 32)) + bias[3];
            *reinterpret_cast<float4*>(g_xg + (size_t)m * (4*HID) + n0 + tx*4) = o;
        }
        __threadfence();
        BAR_VOCAB();
        if (tid == 0) atomicAdd(&g_xg_ready[yy], 1);
    }
}

// ---- vocab mma role: tiles 128x256, warp tile 32x64, bulk-copy loading ----
__device__ __forceinline__ void vocab_role(char* vsm_raw, const float* __restrict__ bv,
                                           float* __restrict__ out, int tid,
                                           uint32_t mb0, uint32_t mb1) {
    __shared__ int s_ti;
    const uint32_t smem = smem_u32(vsm_raw);
    const int wid  = tid >> 5;
    const int lane = tid & 31;
    const int wm   = wid >> 2;
    const int wn   = wid & 3;
    int ph0 = 0, ph1 = 0;

    // ensure Wv conversion complete before any B bulk-load (one-time)
    if (tid == 0) {
        while (*((volatile int*)&g_cvtdone) < NBLK) { __nanosleep(128); }
    }
    BAR_VOCAB();
    __threadfence();

    for (;;) {
        if (tid == 0) s_ti = atomicAdd(&g_tile, 1);
        BAR_VOCAB();
        const int ti = s_ti;
        if (ti >= N_TILES) break;
        const int yy = ti / 125;
        const int n0 = (ti - yy * 125) * 256;
        const int m0 = yy * 128;

        if (tid == 0) {
            unsigned need = (unsigned)((yy * 4 + 5) * NBLK_LSTM);   // +128 h0 arrivals
            while (*((volatile unsigned*)&g_barrier) < need) { __nanosleep(128); }
        }
        BAR_VOCAB();
        __threadfence();

        float acc[2][8][4];
        #pragma unroll
        for (int i = 0; i < 2; i++)
            #pragma unroll
            for (int j = 0; j < 8; j++)
                #pragma unroll
                for (int q = 0; q < 4; q++) acc[i][j][q] = 0.f;

        auto issue = [&](int chunk) {
            if (tid == 0) {
                const int s = chunk & 1;
                const uint32_t mb = s ? mb1 : mb0;
                const uint32_t stage = smem + (uint32_t)s * VG_STAGE;
                MBARRIER_EXPECT_TX(mb, 49152u);
                const char* asrc = reinterpret_cast<const char*>(g_h_c)
                                 + (size_t)chunk * ((size_t)M_ROWS * 128) + (size_t)m0 * 128;
                const char* bsrc = reinterpret_cast<const char*>(g_wv_c)
                                 + (size_t)chunk * ((size_t)VOCAB * 128) + (size_t)n0 * 128;
                bulk_g2s(stage, asrc, 16384u, mb);
                bulk_g2s(stage + 16384u, bsrc, 32768u, mb);
            }
        };

        issue(0);

        for (int chunk = 0; chunk < 8; chunk++) {
            if (chunk + 1 < 8) issue(chunk + 1);
            if (chunk & 1) { MBARRIER_WAIT_PARITY(mb1, ph1); ph1 ^= 1; }
            else           { MBARRIER_WAIT_PARITY(mb0, ph0); ph0 ^= 1; }

            const uint32_t stage = smem + (uint32_t)(chunk & 1) * VG_STAGE;
            const uint32_t aBase = stage;
            const uint32_t bBase = stage + 16384u;

            #pragma unroll
            for (int ks = 0; ks < 4; ks++) {
                uint32_t ah[2][4];
                #pragma unroll
                for (int mt = 0; mt < 2; mt++) {
                    int row = wm * 32 + mt * 16 + (lane & 7) + ((lane >> 3) & 1) * 8;
                    int ch  = ks * 2 + (lane >> 4);
                    uint32_t off = (uint32_t)(row * 128) + (uint32_t)((ch ^ (row & 7)) * 16);
                    ldsm_x4(ah[mt][0], ah[mt][1], ah[mt][2], ah[mt][3], aBase + off);
                }
                // process p in pairs: load 2 B fragments, then 16 mmas
                #pragma unroll
                for (int pp = 0; pp < 2; pp++) {
                    uint32_t bf[2][4];
                    #pragma unroll
                    for (int pi = 0; pi < 2; pi++) {
                        int p   = pp * 2 + pi;
                        int g   = lane >> 3;
                        int row = wn * 64 + p * 16 + (g & 1) * 8 + (lane & 7);
                        int ch  = ks * 2 + (g >> 1);
                        uint32_t off = (uint32_t)(row * 128) + (uint32_t)((ch ^ (row & 7)) * 16);
                        ldsm_x4(bf[pi][0], bf[pi][1], bf[pi][2], bf[pi][3], bBase + off);
                    }
                    #pragma unroll
                    for (int pi = 0; pi < 2; pi++) {
                        int p = pp * 2 + pi;
                        #pragma unroll
                        for (int mt = 0; mt < 2; mt++) {
                            #pragma unroll
                            for (int q = 0; q < 2; q++) {
                                int nt = p * 2 + q;
                                mma_f16(acc[mt][nt], ah[mt][0], ah[mt][1], ah[mt][2], ah[mt][3],
                                        bf[pi][q], bf[pi][q + 2]);
                            }
                        }
                    }
                }
            }
            BAR_VOCAB();   // all warps done with this stage before tid0 refills it
        }

        #pragma unroll
        for (int mt = 0; mt < 2; mt++) {
            int gm0 = m0 + wm * 32 + mt * 16 + (lane >> 2);
            int gm1 = gm0 + 8;
            size_t ob0 = ((size_t)(gm0 & 31) * TT + (size_t)(gm0 >> 5)) * (size_t)VOCAB;
            size_t ob1 = ((size_t)(gm1 & 31) * TT + (size_t)(gm1 >> 5)) * (size_t)VOCAB;
            #pragma unroll
            for (int nt = 0; nt < 8; nt++) {
                int gn = n0 + wn * 64 + nt * 8 + (lane & 3) * 2;
                float bv0 = __ldg(bv + gn), bv1 = __ldg(bv + gn + 1);
                float2 v0 = make_float2(acc[mt][nt][0] + bv0, acc[mt][nt][1] + bv1);
                float2 v1 = make_float2(acc[mt][nt][2] + bv0, acc[mt][nt][3] + bv1);
                *reinterpret_cast<float2*>(out + ob0 + gn) = v0;
                *reinterpret_cast<float2*>(out + ob1 + gn) = v1;
            }
        }
    }
}

__global__ __launch_bounds__(640, 1)
void fused_kernel(const float* __restrict__ Whh, const float* __restrict__ bv,
                  float* __restrict__ out,
                  const float* __restrict__ emb, const float* __restrict__ Wih,
                  const float* __restrict__ b_ih, const float* __restrict__ b_hh,
                  const float* __restrict__ Wv,
                  const float* __restrict__ fc_w, const float* __restrict__ fc_b)
{
    extern __shared__ char sm_raw[];
    __shared__ uint64_t s_mbar[2];
    const int tid = threadIdx.x;
    if (tid >= 512) {
        if (blockIdx.x < NBLK_LSTM)
            lstm_role(reinterpret_cast<float*>(sm_raw), Whh, fc_w, fc_b, tid - 512);
        return;
    }
    const uint32_t mb0 = smem_u32(&s_mbar[0]);
    const uint32_t mb1 = smem_u32(&s_mbar[1]);
    if (tid == 0) {
        MBARRIER_INIT(mb0, 1);
        MBARRIER_INIT(mb1, 1);
    }
    BAR_VOCAB();
    cvt_phase(Wv, tid);
    gates_role(reinterpret_cast<float*>(sm_raw + LSTM_SMEM_BYTES), emb, Wih, b_ih, b_hh, tid);
    vocab_role(sm_raw + LSTM_SMEM_BYTES, bv, out, tid, mb0, mb1);
}

// ---------------------------------------------------------------------------
// launch: 2 kernels only
// ---------------------------------------------------------------------------
extern "C" void kernel_launch(void* const* d_in, const int* in_sizes, int n_in,
                              void* d_out, int out_size) {
    const float* features  = (const float*)d_in[0];
    const int*   reports   = (const int*)  d_in[1];
    const float* emb_table = (const float*)d_in[2];
    const float* fc_w      = (const float*)d_in[3];
    const float* fc_b      = (const float*)d_in[4];
    const float* W_ih      = (const float*)d_in[5];
    const float* b_ih      = (const float*)d_in[6];
    const float* W_hh      = (const float*)d_in[7];
    const float* b_hh      = (const float*)d_in[8];
    const float* Wv        = (const float*)d_in[9];
    const float* bv        = (const float*)d_in[10];
    float* out = (float*)d_out;

    cudaFuncSetAttribute(fused_kernel, cudaFuncAttributeMaxDynamicSharedMemorySize, FUSED_SMEM);

    // K0: prep + pool + counters
    prep_pool_kernel<<<(BATCH * FEAT + 255) / 256, 256>>>(reports, features);
    // K1: fused cvt + h0 + gates + LSTM + vocab (one wave of 148 blocks)
    fused_kernel<<<NBLK, 640, FUSED_SMEM>>>(W_hh, bv, out, emb_table, W_ih, b_ih, b_hh,
                                            Wv, fc_w, fc_b);
}